// round 1
// baseline (speedup 1.0000x reference)
#include <cuda_runtime.h>
#include <cstdint>

#define B_  8
#define C_  512
#define H_  32
#define W_  32
#define NH_ 8
#define DH_ 64
#define HW_ 1024
#define C3_ (3*C_)

// ---------------- scratch (device globals; no allocation allowed) ----------
__device__ float g_t  [(size_t)B_*HW_*C_];     // [B*HW, C]  tokens + pos
__device__ float g_qkv[(size_t)B_*HW_*C3_];    // [B*HW, 3C]
__device__ float g_rs [(size_t)B_*NH_*DH_];    // temp/(|q_d||k_d|) per (b,h,d)
__device__ float g_S  [(size_t)B_*NH_*HW_*HW_];// [B*NH, HW, HW] scores/probs
__device__ float g_o  [(size_t)B_*HW_*C_];     // attn out [B*HW, C]
__device__ float g_ob [(size_t)B_*HW_*C_];     // proj out [B*HW, C]
__device__ float g_y  [(size_t)B_*C_*HW_];     // post-LN + residual [B, C, HW]
__device__ float g_dw [(size_t)B_*C_*HW_];     // depthwise conv out

// ---------------- 1) t = transpose(x) + pos_embed ---------------------------
__global__ void build_t_kernel(const float* __restrict__ x,
                               const float* __restrict__ pos,
                               float* __restrict__ t) {
    __shared__ float tile[32][33];
    int b  = blockIdx.z;
    int n0 = blockIdx.x * 32;   // token
    int c0 = blockIdx.y * 32;   // channel
    int tx = threadIdx.x, ty = threadIdx.y;  // 32 x 8
#pragma unroll
    for (int i = 0; i < 4; i++) {
        int c = c0 + ty + i * 8;
        tile[ty + i * 8][tx] = x[((size_t)b * C_ + c) * HW_ + n0 + tx];
    }
    __syncthreads();
#pragma unroll
    for (int i = 0; i < 4; i++) {
        int n = n0 + ty + i * 8;
        int c = c0 + tx;
        t[((size_t)b * HW_ + n) * C_ + c] = tile[tx][ty + i * 8] + pos[(size_t)n * C_ + c];
    }
}

// ---------------- generic NT GEMM: C[m,n] = sum_k A[m,k]*Bm[n,k] (+bias) ----
// BM=BN=64, BK=16, 256 threads, 4x4 per thread. M,N mult of 64; K mult of 16.
__global__ void gemm_nt_kernel(const float* __restrict__ A,
                               const float* __restrict__ Bm,
                               const float* __restrict__ bias,
                               float* __restrict__ Cm,
                               int M, int N, int K) {
    __shared__ float As[16][68];
    __shared__ float Bs[16][68];
    int tid = threadIdx.x;
    int tx = tid & 15, ty = tid >> 4;
    int m0 = blockIdx.y * 64, n0 = blockIdx.x * 64;
    float acc[4][4] = {};
    int r = tid >> 2, c = tid & 3;
    for (int k0 = 0; k0 < K; k0 += 16) {
        float4 va = *(const float4*)&A [((size_t)(m0 + r)) * K + k0 + c * 4];
        float4 vb = *(const float4*)&Bm[((size_t)(n0 + r)) * K + k0 + c * 4];
        As[c*4+0][r] = va.x; As[c*4+1][r] = va.y; As[c*4+2][r] = va.z; As[c*4+3][r] = va.w;
        Bs[c*4+0][r] = vb.x; Bs[c*4+1][r] = vb.y; Bs[c*4+2][r] = vb.z; Bs[c*4+3][r] = vb.w;
        __syncthreads();
#pragma unroll
        for (int kk = 0; kk < 16; kk++) {
            float4 a4 = *(const float4*)&As[kk][ty * 4];
            float4 b4 = *(const float4*)&Bs[kk][tx * 4];
            float av[4] = {a4.x, a4.y, a4.z, a4.w};
            float bv[4] = {b4.x, b4.y, b4.z, b4.w};
#pragma unroll
            for (int i = 0; i < 4; i++)
#pragma unroll
                for (int j = 0; j < 4; j++) acc[i][j] += av[i] * bv[j];
        }
        __syncthreads();
    }
#pragma unroll
    for (int i = 0; i < 4; i++) {
        int m = m0 + ty * 4 + i;
#pragma unroll
        for (int j = 0; j < 4; j++) {
            int n = n0 + tx * 4 + j;
            float v = acc[i][j];
            if (bias) v += bias[n];
            Cm[(size_t)m * N + n] = v;
        }
    }
}

// ---------------- 3) per-(b,h,d) column norms of q,k -> rs ------------------
__global__ void compute_rs_kernel(const float* __restrict__ qkv,
                                  const float* __restrict__ temp,
                                  float* __restrict__ rs) {
    int bh = blockIdx.x;                     // B*NH
    int b = bh / NH_, h = bh % NH_;
    int d = threadIdx.x & 63;
    int part = threadIdx.x >> 6;             // 0..3
    float sq = 0.f, sk = 0.f;
    size_t base = (size_t)b * HW_ * C3_ + h * DH_ + d;
    for (int n = part; n < HW_; n += 4) {
        float qv = qkv[base + (size_t)n * C3_];
        float kv = qkv[base + (size_t)n * C3_ + C_];
        sq += qv * qv;
        sk += kv * kv;
    }
    __shared__ float smq[4][64], smk[4][64];
    smq[part][d] = sq; smk[part][d] = sk;
    __syncthreads();
    if (threadIdx.x < 64) {
        float q = smq[0][d] + smq[1][d] + smq[2][d] + smq[3][d];
        float k = smk[0][d] + smk[1][d] + smk[2][d] + smk[3][d];
        float qn = fmaxf(sqrtf(q), 1e-12f);
        float kn = fmaxf(sqrtf(k), 1e-12f);
        rs[(size_t)bh * DH_ + d] = temp[h] / (qn * kn);
    }
}

// ---------------- 4) S = (q * rs) . k per (b,h), 64x64 tiles, K=64 ---------
__global__ void attn_score_kernel(const float* __restrict__ qkv,
                                  const float* __restrict__ rs,
                                  float* __restrict__ S) {
    __shared__ float Qs[64][68];
    __shared__ float Ks[64][68];
    int bh = blockIdx.z;
    int b = bh / NH_, h = bh % NH_;
    int n0 = blockIdx.y * 64;   // query rows
    int m0 = blockIdx.x * 64;   // key cols
    int tid = threadIdx.x;
    int tx = tid & 15, ty = tid >> 4;
    int r = tid >> 2, c = tid & 3;

    size_t qbase = ((size_t)b * HW_ + n0 + r) * C3_ + h * DH_;
    size_t kbase = ((size_t)b * HW_ + m0 + r) * C3_ + C_ + h * DH_;
    size_t rsb   = (size_t)bh * DH_;
#pragma unroll
    for (int j = 0; j < 4; j++) {
        int chunk = c + 4 * j;            // 0..15, d = chunk*4
        float4 vq = *(const float4*)&qkv[qbase + chunk * 4];
        float4 vk = *(const float4*)&qkv[kbase + chunk * 4];
        float4 vr = *(const float4*)&rs[rsb + chunk * 4];
        Qs[chunk*4+0][r] = vq.x; Qs[chunk*4+1][r] = vq.y;
        Qs[chunk*4+2][r] = vq.z; Qs[chunk*4+3][r] = vq.w;
        Ks[chunk*4+0][r] = vk.x * vr.x; Ks[chunk*4+1][r] = vk.y * vr.y;
        Ks[chunk*4+2][r] = vk.z * vr.z; Ks[chunk*4+3][r] = vk.w * vr.w;
    }
    __syncthreads();

    float acc[4][4] = {};
#pragma unroll
    for (int kk = 0; kk < 64; kk++) {
        float4 a4 = *(const float4*)&Qs[kk][ty * 4];
        float4 b4 = *(const float4*)&Ks[kk][tx * 4];
        float av[4] = {a4.x, a4.y, a4.z, a4.w};
        float bv[4] = {b4.x, b4.y, b4.z, b4.w};
#pragma unroll
        for (int i = 0; i < 4; i++)
#pragma unroll
            for (int j = 0; j < 4; j++) acc[i][j] += av[i] * bv[j];
    }
#pragma unroll
    for (int i = 0; i < 4; i++) {
        size_t row = (size_t)bh * HW_ + n0 + ty * 4 + i;
#pragma unroll
        for (int j = 0; j < 4; j++)
            S[row * HW_ + m0 + tx * 4 + j] = acc[i][j];
    }
}

// ---------------- 5) row softmax over HW=1024 -------------------------------
__global__ void softmax_kernel(float* __restrict__ S) {
    size_t row = blockIdx.x;
    float* p = S + row * (size_t)HW_;
    int tid = threadIdx.x;  // 256
    float4 v = reinterpret_cast<float4*>(p)[tid];
    __shared__ float red[256];
    float mx = fmaxf(fmaxf(v.x, v.y), fmaxf(v.z, v.w));
    red[tid] = mx; __syncthreads();
    for (int s = 128; s > 0; s >>= 1) {
        if (tid < s) red[tid] = fmaxf(red[tid], red[tid + s]);
        __syncthreads();
    }
    mx = red[0];
    __syncthreads();
    v.x = __expf(v.x - mx); v.y = __expf(v.y - mx);
    v.z = __expf(v.z - mx); v.w = __expf(v.w - mx);
    red[tid] = v.x + v.y + v.z + v.w; __syncthreads();
    for (int s = 128; s > 0; s >>= 1) {
        if (tid < s) red[tid] += red[tid + s];
        __syncthreads();
    }
    float inv = 1.f / red[0];
    v.x *= inv; v.y *= inv; v.z *= inv; v.w *= inv;
    reinterpret_cast<float4*>(p)[tid] = v;
}

// ---------------- 6) O = attn @ V, per (b,h), BM=64 BN=64(full) BK=32 -------
__global__ void attn_out_kernel(const float* __restrict__ S,
                                const float* __restrict__ qkv,
                                float* __restrict__ o) {
    __shared__ float Ss[32][68];
    __shared__ float Vs[32][68];
    int bh = blockIdx.y;
    int b = bh / NH_, h = bh % NH_;
    int n0 = blockIdx.x * 64;
    int tid = threadIdx.x;
    int tx = tid & 15, ty = tid >> 4;
    float acc[4][4] = {};

    for (int m0 = 0; m0 < HW_; m0 += 32) {
        // S tile: 64 rows(n) x 32 cols(m) = 512 float4
#pragma unroll
        for (int it = 0; it < 2; it++) {
            int i = tid + it * 256;
            int n = i >> 3, c8 = i & 7;
            float4 v = *(const float4*)&S[((size_t)bh * HW_ + n0 + n) * HW_ + m0 + c8 * 4];
            Ss[c8*4+0][n] = v.x; Ss[c8*4+1][n] = v.y;
            Ss[c8*4+2][n] = v.z; Ss[c8*4+3][n] = v.w;
        }
        // V tile: 32 rows(m) x 64 cols(d) = 512 float4, stored direct
#pragma unroll
        for (int it = 0; it < 2; it++) {
            int i = tid + it * 256;
            int m = i >> 4, c16 = i & 15;
            float4 v = *(const float4*)&qkv[((size_t)b * HW_ + m0 + m) * C3_ + 2 * C_ + h * DH_ + c16 * 4];
            *(float4*)&Vs[m][c16 * 4] = v;
        }
        __syncthreads();
#pragma unroll
        for (int kk = 0; kk < 32; kk++) {
            float4 a4 = *(const float4*)&Ss[kk][ty * 4];
            float4 b4 = *(const float4*)&Vs[kk][tx * 4];
            float av[4] = {a4.x, a4.y, a4.z, a4.w};
            float bv[4] = {b4.x, b4.y, b4.z, b4.w};
#pragma unroll
            for (int i = 0; i < 4; i++)
#pragma unroll
                for (int j = 0; j < 4; j++) acc[i][j] += av[i] * bv[j];
        }
        __syncthreads();
    }
#pragma unroll
    for (int i = 0; i < 4; i++) {
        int n = n0 + ty * 4 + i;
#pragma unroll
        for (int j = 0; j < 4; j++)
            o[((size_t)b * HW_ + n) * C_ + h * DH_ + tx * 4 + j] = acc[i][j];
    }
}

// ---------------- 8) LayerNorm over C + residual + transpose to [B,C,HW] ----
__global__ void ln_residual_kernel(const float* __restrict__ ob,
                                   const float* __restrict__ x,
                                   const float* __restrict__ g,
                                   const float* __restrict__ be,
                                   float* __restrict__ y) {
    int row = blockIdx.x;            // b*HW + n
    int b = row >> 10, n = row & 1023;
    const float* pr = ob + (size_t)row * C_;
    int tid = threadIdx.x;           // 256
    float v0 = pr[tid], v1 = pr[tid + 256];
    __shared__ float red[256];
    red[tid] = v0 + v1; __syncthreads();
    for (int s = 128; s > 0; s >>= 1) {
        if (tid < s) red[tid] += red[tid + s];
        __syncthreads();
    }
    float mean = red[0] * (1.0f / C_);
    __syncthreads();
    float d0 = v0 - mean, d1 = v1 - mean;
    red[tid] = d0 * d0 + d1 * d1; __syncthreads();
    for (int s = 128; s > 0; s >>= 1) {
        if (tid < s) red[tid] += red[tid + s];
        __syncthreads();
    }
    float rstd = rsqrtf(red[0] * (1.0f / C_) + 1e-5f);
    int c0 = tid, c1 = tid + 256;
    size_t i0 = ((size_t)b * C_ + c0) * HW_ + n;
    size_t i1 = ((size_t)b * C_ + c1) * HW_ + n;
    y[i0] = d0 * rstd * g[c0] + be[c0] + x[i0];
    y[i1] = d1 * rstd * g[c1] + be[c1] + x[i1];
}

// ---------------- 9) depthwise 3x3 SAME -------------------------------------
__global__ void dwconv_kernel(const float* __restrict__ y,
                              const float* __restrict__ w,
                              const float* __restrict__ bias,
                              float* __restrict__ out) {
    int bc = blockIdx.x;                 // B*C
    int c = bc % C_;
    int hw = blockIdx.y * 256 + threadIdx.x;
    int hh = hw >> 5, ww = hw & 31;
    const float* p = y + (size_t)bc * HW_;
    float acc = bias[c];
#pragma unroll
    for (int ki = 0; ki < 3; ki++) {
        int ih = hh + ki - 1;
        if (ih < 0 || ih >= H_) continue;
#pragma unroll
        for (int kj = 0; kj < 3; kj++) {
            int iw = ww + kj - 1;
            if (iw < 0 || iw >= W_) continue;
            acc += w[c * 9 + ki * 3 + kj] * p[ih * W_ + iw];
        }
    }
    out[(size_t)bc * HW_ + hw] = acc;
}

// ---------------- 10) pointwise conv (NN GEMM) + bias + residual -> d_out ---
__global__ void pw_final_kernel(const float* __restrict__ pw_w,
                                const float* __restrict__ dw,
                                const float* __restrict__ y,
                                const float* __restrict__ pw_b,
                                float* __restrict__ out) {
    __shared__ float As[16][68];
    __shared__ float Bs[16][68];
    int b = blockIdx.z;
    int m0 = blockIdx.y * 64;   // out channel
    int n0 = blockIdx.x * 64;   // hw
    int tid = threadIdx.x;
    int tx = tid & 15, ty = tid >> 4;
    const float* Bb = dw + (size_t)b * C_ * HW_;
    float acc[4][4] = {};
    int ra = tid >> 2, ca = tid & 3;     // A loader: 64 rows x 4 float4
    int rb = tid >> 4, cb = tid & 15;    // B loader: 16 rows x 16 float4
    for (int k0 = 0; k0 < C_; k0 += 16) {
        float4 va = *(const float4*)&pw_w[((size_t)(m0 + ra)) * C_ + k0 + ca * 4];
        As[ca*4+0][ra] = va.x; As[ca*4+1][ra] = va.y;
        As[ca*4+2][ra] = va.z; As[ca*4+3][ra] = va.w;
        float4 vb = *(const float4*)&Bb[((size_t)(k0 + rb)) * HW_ + n0 + cb * 4];
        *(float4*)&Bs[rb][cb * 4] = vb;
        __syncthreads();
#pragma unroll
        for (int kk = 0; kk < 16; kk++) {
            float4 a4 = *(const float4*)&As[kk][ty * 4];
            float4 b4 = *(const float4*)&Bs[kk][tx * 4];
            float av[4] = {a4.x, a4.y, a4.z, a4.w};
            float bv[4] = {b4.x, b4.y, b4.z, b4.w};
#pragma unroll
            for (int i = 0; i < 4; i++)
#pragma unroll
                for (int j = 0; j < 4; j++) acc[i][j] += av[i] * bv[j];
        }
        __syncthreads();
    }
#pragma unroll
    for (int i = 0; i < 4; i++) {
        int m = m0 + ty * 4 + i;
#pragma unroll
        for (int j = 0; j < 4; j++) {
            int n = n0 + tx * 4 + j;
            size_t idx = ((size_t)b * C_ + m) * HW_ + n;
            out[idx] = acc[i][j] + pw_b[m] + y[idx];
        }
    }
}

// ---------------- launch -----------------------------------------------------
extern "C" void kernel_launch(void* const* d_in, const int* in_sizes, int n_in,
                              void* d_out, int out_size) {
    const float* x      = (const float*)d_in[0];
    const float* qkv_w  = (const float*)d_in[1];
    const float* proj_w = (const float*)d_in[2];
    const float* proj_b = (const float*)d_in[3];
    const float* temper = (const float*)d_in[4];
    const float* ln_g   = (const float*)d_in[5];
    const float* ln_b   = (const float*)d_in[6];
    const float* pos    = (const float*)d_in[7];
    const float* dw_w   = (const float*)d_in[8];
    const float* dw_b   = (const float*)d_in[9];
    const float* pw_w   = (const float*)d_in[10];
    const float* pw_b   = (const float*)d_in[11];
    float* out = (float*)d_out;

    float *t, *qkv, *rs, *S, *o, *ob, *y, *dw;
    cudaGetSymbolAddress((void**)&t,   g_t);
    cudaGetSymbolAddress((void**)&qkv, g_qkv);
    cudaGetSymbolAddress((void**)&rs,  g_rs);
    cudaGetSymbolAddress((void**)&S,   g_S);
    cudaGetSymbolAddress((void**)&o,   g_o);
    cudaGetSymbolAddress((void**)&ob,  g_ob);
    cudaGetSymbolAddress((void**)&y,   g_y);
    cudaGetSymbolAddress((void**)&dw,  g_dw);

    // 1) t = transpose(x) + pos
    build_t_kernel<<<dim3(HW_/32, C_/32, B_), dim3(32, 8)>>>(x, pos, t);
    // 2) qkv = t @ qkv_w^T
    gemm_nt_kernel<<<dim3(C3_/64, (B_*HW_)/64), 256>>>(t, qkv_w, nullptr, qkv,
                                                       B_*HW_, C3_, C_);
    // 3) column-norm scales
    compute_rs_kernel<<<B_*NH_, 256>>>(qkv, temper, rs);
    // 4) scores
    attn_score_kernel<<<dim3(HW_/64, HW_/64, B_*NH_), 256>>>(qkv, rs, S);
    // 5) softmax
    softmax_kernel<<<B_*NH_*HW_, 256>>>(S);
    // 6) O = attn @ V
    attn_out_kernel<<<dim3(HW_/64, B_*NH_), 256>>>(S, qkv, o);
    // 7) proj
    gemm_nt_kernel<<<dim3(C_/64, (B_*HW_)/64), 256>>>(o, proj_w, proj_b, ob,
                                                      B_*HW_, C_, C_);
    // 8) LN + residual + transpose to [B,C,HW]
    ln_residual_kernel<<<B_*HW_, 256>>>(ob, x, ln_g, ln_b, y);
    // 9) depthwise 3x3
    dwconv_kernel<<<dim3(B_*C_, HW_/256), 256>>>(y, dw_w, dw_b, dw);
    // 10) pointwise + residual -> out
    pw_final_kernel<<<dim3(HW_/64, C_/64, B_), 256>>>(pw_w, dw, y, pw_b, out);
}

// round 2
// speedup vs baseline: 1.2478x; 1.2478x over previous
#include <cuda_runtime.h>
#include <cstdint>

#define B_  8
#define C_  512
#define H_  32
#define W_  32
#define NH_ 8
#define DH_ 64
#define HW_ 1024
#define C3_ (3*C_)

// ---------------- scratch (device globals; no allocation allowed) ----------
__device__ float g_t  [(size_t)B_*HW_*C_];     // [B*HW, C]  tokens + pos
__device__ float g_qkv[(size_t)B_*HW_*C3_];    // [B*HW, 3C]
__device__ float g_rs [(size_t)B_*NH_*DH_];    // temp/(|q_d||k_d|) per (b,h,d)
__device__ float g_o  [(size_t)B_*HW_*C_];     // attn out [B*HW, C]
__device__ float g_ob [(size_t)B_*HW_*C_];     // proj out [B*HW, C]
__device__ float g_y  [(size_t)B_*C_*HW_];     // post-LN + residual [B, C, HW]
__device__ float g_dw [(size_t)B_*C_*HW_];     // depthwise conv out

// ---------------- 1) t = transpose(x) + pos_embed ---------------------------
__global__ void build_t_kernel(const float* __restrict__ x,
                               const float* __restrict__ pos,
                               float* __restrict__ t) {
    __shared__ float tile[32][33];
    int b  = blockIdx.z;
    int n0 = blockIdx.x * 32;   // token
    int c0 = blockIdx.y * 32;   // channel
    int tx = threadIdx.x, ty = threadIdx.y;  // 32 x 8
#pragma unroll
    for (int i = 0; i < 4; i++) {
        int c = c0 + ty + i * 8;
        tile[ty + i * 8][tx] = x[((size_t)b * C_ + c) * HW_ + n0 + tx];
    }
    __syncthreads();
#pragma unroll
    for (int i = 0; i < 4; i++) {
        int n = n0 + ty + i * 8;
        int c = c0 + tx;
        t[((size_t)b * HW_ + n) * C_ + c] = tile[tx][ty + i * 8] + pos[(size_t)n * C_ + c];
    }
}

// ---------------- NT GEMM 128x128x16, 8x8/thread ---------------------------
// C[m,n] = sum_k A[m,k]*Bm[n,k] (+bias[n]). M,N mult of 128; K mult of 16.
__global__ __launch_bounds__(256, 2)
void gemm128_nt_kernel(const float* __restrict__ A,
                       const float* __restrict__ Bm,
                       const float* __restrict__ bias,
                       float* __restrict__ Cm,
                       int M, int N, int K) {
    __shared__ float As[16 * 132];   // As[k][m]
    __shared__ float Bs[16 * 132];   // Bs[k][n]
    int tid = threadIdx.x;
    int tx = tid & 15, ty = tid >> 4;
    int m0 = blockIdx.y * 128, n0 = blockIdx.x * 128;
    float acc[8][8] = {};
    int lr = tid >> 2;            // 0..63
    int lc = (tid & 3) * 4;       // 0,4,8,12

    for (int k0 = 0; k0 < K; k0 += 16) {
#pragma unroll
        for (int it = 0; it < 2; it++) {
            int row = lr + it * 64;
            float4 va = *(const float4*)&A [(size_t)(m0 + row) * K + k0 + lc];
            As[(lc + 0) * 132 + row] = va.x;
            As[(lc + 1) * 132 + row] = va.y;
            As[(lc + 2) * 132 + row] = va.z;
            As[(lc + 3) * 132 + row] = va.w;
            float4 vb = *(const float4*)&Bm[(size_t)(n0 + row) * K + k0 + lc];
            Bs[(lc + 0) * 132 + row] = vb.x;
            Bs[(lc + 1) * 132 + row] = vb.y;
            Bs[(lc + 2) * 132 + row] = vb.z;
            Bs[(lc + 3) * 132 + row] = vb.w;
        }
        __syncthreads();
#pragma unroll
        for (int kk = 0; kk < 16; kk++) {
            float4 a0 = *(const float4*)&As[kk * 132 + ty * 8];
            float4 a1 = *(const float4*)&As[kk * 132 + ty * 8 + 4];
            float4 b0 = *(const float4*)&Bs[kk * 132 + tx * 8];
            float4 b1 = *(const float4*)&Bs[kk * 132 + tx * 8 + 4];
            float av[8] = {a0.x, a0.y, a0.z, a0.w, a1.x, a1.y, a1.z, a1.w};
            float bv[8] = {b0.x, b0.y, b0.z, b0.w, b1.x, b1.y, b1.z, b1.w};
#pragma unroll
            for (int i = 0; i < 8; i++)
#pragma unroll
                for (int j = 0; j < 8; j++) acc[i][j] = fmaf(av[i], bv[j], acc[i][j]);
        }
        __syncthreads();
    }
#pragma unroll
    for (int i = 0; i < 8; i++) {
        int m = m0 + ty * 8 + i;
#pragma unroll
        for (int jj = 0; jj < 2; jj++) {
            int n = n0 + tx * 8 + jj * 4;
            float4 r;
            r.x = acc[i][jj * 4 + 0];
            r.y = acc[i][jj * 4 + 1];
            r.z = acc[i][jj * 4 + 2];
            r.w = acc[i][jj * 4 + 3];
            if (bias) {
                r.x += bias[n + 0]; r.y += bias[n + 1];
                r.z += bias[n + 2]; r.w += bias[n + 3];
            }
            *(float4*)&Cm[(size_t)m * N + n] = r;
        }
    }
}

// ---------------- 3) per-(b,h,d) column norms of q,k -> rs ------------------
__global__ void compute_rs_kernel(const float* __restrict__ qkv,
                                  const float* __restrict__ temp,
                                  float* __restrict__ rs) {
    int bh = blockIdx.x;                     // B*NH
    int b = bh / NH_, h = bh % NH_;
    int d = threadIdx.x & 63;
    int part = threadIdx.x >> 6;             // 0..3
    float sq = 0.f, sk = 0.f;
    size_t base = (size_t)b * HW_ * C3_ + h * DH_ + d;
    for (int n = part; n < HW_; n += 4) {
        float qv = qkv[base + (size_t)n * C3_];
        float kv = qkv[base + (size_t)n * C3_ + C_];
        sq += qv * qv;
        sk += kv * kv;
    }
    __shared__ float smq[4][64], smk[4][64];
    smq[part][d] = sq; smk[part][d] = sk;
    __syncthreads();
    if (threadIdx.x < 64) {
        float q = smq[0][d] + smq[1][d] + smq[2][d] + smq[3][d];
        float k = smk[0][d] + smk[1][d] + smk[2][d] + smk[3][d];
        float qn = fmaxf(sqrtf(q), 1e-12f);
        float kn = fmaxf(sqrtf(k), 1e-12f);
        rs[(size_t)bh * DH_ + d] = temp[h] / (qn * kn);
    }
}

// ---------------- 4) fused flash attention ---------------------------------
// Per block: (bh, 128 query rows). Online softmax, P staged via smem.
// threads 256: tx=tid&15 -> 4 keys / 4 out-dims, ty=tid>>4 -> 8 rows.
#define FA_SMEM ((64*132 + 64*68 + 64*68 + 128*68 + 64) * 4)
__global__ __launch_bounds__(256, 2)
void fused_attn_kernel(const float* __restrict__ qkv,
                       const float* __restrict__ rs,
                       float* __restrict__ o) {
    extern __shared__ float sm[];
    float* Qs  = sm;                    // [64 d][132] (128 rows + pad)
    float* Ks  = Qs + 64 * 132;        // [64 d][68]  (64 keys + pad)
    float* Vs  = Ks + 64 * 68;         // [64 key][68] (64 d + pad)
    float* Ps  = Vs + 64 * 68;         // [128 row][68] (64 keys + pad)
    float* rss = Ps + 128 * 68;        // [64]

    int bh = blockIdx.y;
    int b = bh >> 3, h = bh & 7;
    int q0 = blockIdx.x * 128;
    int tid = threadIdx.x;
    int tx = tid & 15, ty = tid >> 4;

    if (tid < 64) rss[tid] = rs[bh * 64 + tid];
    __syncthreads();

    // load Q tile scaled by rs, transposed to d-major
#pragma unroll
    for (int v = 0; v < 8; v++) {
        int idx = v * 256 + tid;
        int row = idx >> 4, d = (idx & 15) * 4;
        float4 q = *(const float4*)&qkv[((size_t)(b * HW_ + q0 + row)) * C3_ + h * DH_ + d];
        Qs[(d + 0) * 132 + row] = q.x * rss[d + 0];
        Qs[(d + 1) * 132 + row] = q.y * rss[d + 1];
        Qs[(d + 2) * 132 + row] = q.z * rss[d + 2];
        Qs[(d + 3) * 132 + row] = q.w * rss[d + 3];
    }

    float m[8], l[8], acc[8][4];
#pragma unroll
    for (int i = 0; i < 8; i++) {
        m[i] = -1e30f; l[i] = 0.f;
#pragma unroll
        for (int j = 0; j < 4; j++) acc[i][j] = 0.f;
    }

    for (int kt = 0; kt < 16; kt++) {
        int k0 = kt * 64;
        __syncthreads();   // Ks/Vs/Ps consumers of previous iter done
        // load K (transposed) and V (direct)
#pragma unroll
        for (int v = 0; v < 4; v++) {
            int idx = v * 256 + tid;
            int row = idx >> 4, d = (idx & 15) * 4;
            size_t base = ((size_t)(b * HW_ + k0 + row)) * C3_ + h * DH_ + d;
            float4 k4 = *(const float4*)&qkv[base + C_];
            Ks[(d + 0) * 68 + row] = k4.x;
            Ks[(d + 1) * 68 + row] = k4.y;
            Ks[(d + 2) * 68 + row] = k4.z;
            Ks[(d + 3) * 68 + row] = k4.w;
            float4 v4 = *(const float4*)&qkv[base + 2 * C_];
            *(float4*)&Vs[row * 68 + d] = v4;
        }
        __syncthreads();

        // S = Q . K  (8 rows x 4 keys per thread)
        float s[8][4] = {};
#pragma unroll 8
        for (int kk = 0; kk < 64; kk++) {
            float4 a0 = *(const float4*)&Qs[kk * 132 + ty * 8];
            float4 a1 = *(const float4*)&Qs[kk * 132 + ty * 8 + 4];
            float4 bb = *(const float4*)&Ks[kk * 68 + tx * 4];
            float av[8] = {a0.x, a0.y, a0.z, a0.w, a1.x, a1.y, a1.z, a1.w};
            float bv[4] = {bb.x, bb.y, bb.z, bb.w};
#pragma unroll
            for (int i = 0; i < 8; i++)
#pragma unroll
                for (int j = 0; j < 4; j++) s[i][j] = fmaf(av[i], bv[j], s[i][j]);
        }

        // online softmax per row (reduce across 16 lanes sharing a row)
#pragma unroll
        for (int i = 0; i < 8; i++) {
            float mx = fmaxf(fmaxf(s[i][0], s[i][1]), fmaxf(s[i][2], s[i][3]));
#pragma unroll
            for (int off = 8; off; off >>= 1)
                mx = fmaxf(mx, __shfl_xor_sync(0xffffffffu, mx, off, 16));
            float mnew = fmaxf(m[i], mx);
            float alpha = __expf(m[i] - mnew);
            float p0 = __expf(s[i][0] - mnew);
            float p1 = __expf(s[i][1] - mnew);
            float p2 = __expf(s[i][2] - mnew);
            float p3 = __expf(s[i][3] - mnew);
            float sum = (p0 + p1) + (p2 + p3);
#pragma unroll
            for (int off = 8; off; off >>= 1)
                sum += __shfl_xor_sync(0xffffffffu, sum, off, 16);
            l[i] = l[i] * alpha + sum;
            m[i] = mnew;
            acc[i][0] *= alpha; acc[i][1] *= alpha;
            acc[i][2] *= alpha; acc[i][3] *= alpha;
            float4 pr; pr.x = p0; pr.y = p1; pr.z = p2; pr.w = p3;
            *(float4*)&Ps[(ty * 8 + i) * 68 + tx * 4] = pr;
        }
        __syncthreads();

        // O += P . V  (kk over keys, step 4 with float4 a-loads)
#pragma unroll 4
        for (int kk = 0; kk < 64; kk += 4) {
            float4 b0 = *(const float4*)&Vs[(kk + 0) * 68 + tx * 4];
            float4 b1 = *(const float4*)&Vs[(kk + 1) * 68 + tx * 4];
            float4 b2 = *(const float4*)&Vs[(kk + 2) * 68 + tx * 4];
            float4 b3 = *(const float4*)&Vs[(kk + 3) * 68 + tx * 4];
#pragma unroll
            for (int i = 0; i < 8; i++) {
                float4 a4 = *(const float4*)&Ps[(ty * 8 + i) * 68 + kk];
                acc[i][0] = fmaf(a4.x, b0.x, acc[i][0]);
                acc[i][1] = fmaf(a4.x, b0.y, acc[i][1]);
                acc[i][2] = fmaf(a4.x, b0.z, acc[i][2]);
                acc[i][3] = fmaf(a4.x, b0.w, acc[i][3]);
                acc[i][0] = fmaf(a4.y, b1.x, acc[i][0]);
                acc[i][1] = fmaf(a4.y, b1.y, acc[i][1]);
                acc[i][2] = fmaf(a4.y, b1.z, acc[i][2]);
                acc[i][3] = fmaf(a4.y, b1.w, acc[i][3]);
                acc[i][0] = fmaf(a4.z, b2.x, acc[i][0]);
                acc[i][1] = fmaf(a4.z, b2.y, acc[i][1]);
                acc[i][2] = fmaf(a4.z, b2.z, acc[i][2]);
                acc[i][3] = fmaf(a4.z, b2.w, acc[i][3]);
                acc[i][0] = fmaf(a4.w, b3.x, acc[i][0]);
                acc[i][1] = fmaf(a4.w, b3.y, acc[i][1]);
                acc[i][2] = fmaf(a4.w, b3.z, acc[i][2]);
                acc[i][3] = fmaf(a4.w, b3.w, acc[i][3]);
            }
        }
    }

    // epilogue: normalize and store
#pragma unroll
    for (int i = 0; i < 8; i++) {
        float inv = 1.f / l[i];
        float4 r;
        r.x = acc[i][0] * inv; r.y = acc[i][1] * inv;
        r.z = acc[i][2] * inv; r.w = acc[i][3] * inv;
        int n = q0 + ty * 8 + i;
        *(float4*)&o[((size_t)(b * HW_ + n)) * C_ + h * DH_ + tx * 4] = r;
    }
}

// ---------------- 8) LayerNorm over C + residual + transpose to [B,C,HW] ----
__global__ void ln_residual_kernel(const float* __restrict__ ob,
                                   const float* __restrict__ x,
                                   const float* __restrict__ g,
                                   const float* __restrict__ be,
                                   float* __restrict__ y) {
    int row = blockIdx.x;            // b*HW + n
    int b = row >> 10, n = row & 1023;
    const float* pr = ob + (size_t)row * C_;
    int tid = threadIdx.x;           // 256
    float v0 = pr[tid], v1 = pr[tid + 256];
    __shared__ float red[256];
    red[tid] = v0 + v1; __syncthreads();
    for (int s = 128; s > 0; s >>= 1) {
        if (tid < s) red[tid] += red[tid + s];
        __syncthreads();
    }
    float mean = red[0] * (1.0f / C_);
    __syncthreads();
    float d0 = v0 - mean, d1 = v1 - mean;
    red[tid] = d0 * d0 + d1 * d1; __syncthreads();
    for (int s = 128; s > 0; s >>= 1) {
        if (tid < s) red[tid] += red[tid + s];
        __syncthreads();
    }
    float rstd = rsqrtf(red[0] * (1.0f / C_) + 1e-5f);
    int c0 = tid, c1 = tid + 256;
    size_t i0 = ((size_t)b * C_ + c0) * HW_ + n;
    size_t i1 = ((size_t)b * C_ + c1) * HW_ + n;
    y[i0] = d0 * rstd * g[c0] + be[c0] + x[i0];
    y[i1] = d1 * rstd * g[c1] + be[c1] + x[i1];
}

// ---------------- 9) depthwise 3x3 SAME -------------------------------------
__global__ void dwconv_kernel(const float* __restrict__ y,
                              const float* __restrict__ w,
                              const float* __restrict__ bias,
                              float* __restrict__ out) {
    int bc = blockIdx.x;                 // B*C
    int c = bc % C_;
    int hw = blockIdx.y * 256 + threadIdx.x;
    int hh = hw >> 5, ww = hw & 31;
    const float* p = y + (size_t)bc * HW_;
    float acc = bias[c];
#pragma unroll
    for (int ki = 0; ki < 3; ki++) {
        int ih = hh + ki - 1;
        if (ih < 0 || ih >= H_) continue;
#pragma unroll
        for (int kj = 0; kj < 3; kj++) {
            int iw = ww + kj - 1;
            if (iw < 0 || iw >= W_) continue;
            acc += w[c * 9 + ki * 3 + kj] * p[ih * W_ + iw];
        }
    }
    out[(size_t)bc * HW_ + hw] = acc;
}

// ---------------- 10) pointwise conv (NN GEMM 128x128) + bias + residual ----
__global__ __launch_bounds__(256, 2)
void pw128_kernel(const float* __restrict__ Aw,
                  const float* __restrict__ dw,
                  const float* __restrict__ yres,
                  const float* __restrict__ bias,
                  float* __restrict__ out) {
    __shared__ float As[16 * 132];   // As[k][m]
    __shared__ float Bs[16 * 132];   // Bs[k][n]
    int b = blockIdx.z;
    int m0 = blockIdx.y * 128, n0 = blockIdx.x * 128;
    int tid = threadIdx.x;
    int tx = tid & 15, ty = tid >> 4;
    const float* Bb = dw + (size_t)b * C_ * HW_;
    float acc[8][8] = {};
    int lr = tid >> 2;
    int lc = (tid & 3) * 4;

    for (int k0 = 0; k0 < C_; k0 += 16) {
#pragma unroll
        for (int it = 0; it < 2; it++) {
            int row = lr + it * 64;
            float4 va = *(const float4*)&Aw[(size_t)(m0 + row) * C_ + k0 + lc];
            As[(lc + 0) * 132 + row] = va.x;
            As[(lc + 1) * 132 + row] = va.y;
            As[(lc + 2) * 132 + row] = va.z;
            As[(lc + 3) * 132 + row] = va.w;
            int idx = it * 256 + tid;
            int rowk = idx >> 5, c32 = (idx & 31) * 4;
            *(float4*)&Bs[rowk * 132 + c32] =
                *(const float4*)&Bb[(size_t)(k0 + rowk) * HW_ + n0 + c32];
        }
        __syncthreads();
#pragma unroll
        for (int kk = 0; kk < 16; kk++) {
            float4 a0 = *(const float4*)&As[kk * 132 + ty * 8];
            float4 a1 = *(const float4*)&As[kk * 132 + ty * 8 + 4];
            float4 b0 = *(const float4*)&Bs[kk * 132 + tx * 8];
            float4 b1 = *(const float4*)&Bs[kk * 132 + tx * 8 + 4];
            float av[8] = {a0.x, a0.y, a0.z, a0.w, a1.x, a1.y, a1.z, a1.w};
            float bv[8] = {b0.x, b0.y, b0.z, b0.w, b1.x, b1.y, b1.z, b1.w};
#pragma unroll
            for (int i = 0; i < 8; i++)
#pragma unroll
                for (int j = 0; j < 8; j++) acc[i][j] = fmaf(av[i], bv[j], acc[i][j]);
        }
        __syncthreads();
    }
#pragma unroll
    for (int i = 0; i < 8; i++) {
        int mr = m0 + ty * 8 + i;
        float bm = bias[mr];
#pragma unroll
        for (int jj = 0; jj < 2; jj++) {
            int n = n0 + tx * 8 + jj * 4;
            size_t idx = ((size_t)b * C_ + mr) * HW_ + n;
            float4 yr = *(const float4*)&yres[idx];
            float4 r;
            r.x = acc[i][jj * 4 + 0] + bm + yr.x;
            r.y = acc[i][jj * 4 + 1] + bm + yr.y;
            r.z = acc[i][jj * 4 + 2] + bm + yr.z;
            r.w = acc[i][jj * 4 + 3] + bm + yr.w;
            *(float4*)&out[idx] = r;
        }
    }
}

// ---------------- launch -----------------------------------------------------
extern "C" void kernel_launch(void* const* d_in, const int* in_sizes, int n_in,
                              void* d_out, int out_size) {
    const float* x      = (const float*)d_in[0];
    const float* qkv_w  = (const float*)d_in[1];
    const float* proj_w = (const float*)d_in[2];
    const float* proj_b = (const float*)d_in[3];
    const float* temper = (const float*)d_in[4];
    const float* ln_g   = (const float*)d_in[5];
    const float* ln_b   = (const float*)d_in[6];
    const float* pos    = (const float*)d_in[7];
    const float* dw_w   = (const float*)d_in[8];
    const float* dw_b   = (const float*)d_in[9];
    const float* pw_w   = (const float*)d_in[10];
    const float* pw_b   = (const float*)d_in[11];
    float* out = (float*)d_out;

    float *t, *qkv, *rs, *o, *ob, *y, *dw;
    cudaGetSymbolAddress((void**)&t,   g_t);
    cudaGetSymbolAddress((void**)&qkv, g_qkv);
    cudaGetSymbolAddress((void**)&rs,  g_rs);
    cudaGetSymbolAddress((void**)&o,   g_o);
    cudaGetSymbolAddress((void**)&ob,  g_ob);
    cudaGetSymbolAddress((void**)&y,   g_y);
    cudaGetSymbolAddress((void**)&dw,  g_dw);

    cudaFuncSetAttribute(fused_attn_kernel,
                         cudaFuncAttributeMaxDynamicSharedMemorySize, FA_SMEM);

    // 1) t = transpose(x) + pos
    build_t_kernel<<<dim3(HW_/32, C_/32, B_), dim3(32, 8)>>>(x, pos, t);
    // 2) qkv = t @ qkv_w^T
    gemm128_nt_kernel<<<dim3(C3_/128, (B_*HW_)/128), 256>>>(t, qkv_w, nullptr, qkv,
                                                            B_*HW_, C3_, C_);
    // 3) column-norm scales
    compute_rs_kernel<<<B_*NH_, 256>>>(qkv, temper, rs);
    // 4) fused attention -> o
    fused_attn_kernel<<<dim3(HW_/128, B_*NH_), 256, FA_SMEM>>>(qkv, rs, o);
    // 5) proj
    gemm128_nt_kernel<<<dim3(C_/128, (B_*HW_)/128), 256>>>(o, proj_w, proj_b, ob,
                                                           B_*HW_, C_, C_);
    // 6) LN + residual + transpose to [B,C,HW]
    ln_residual_kernel<<<B_*HW_, 256>>>(ob, x, ln_g, ln_b, y);
    // 7) depthwise 3x3
    dwconv_kernel<<<dim3(B_*C_, HW_/256), 256>>>(y, dw_w, dw_b, dw);
    // 8) pointwise + residual -> out
    pw128_kernel<<<dim3(HW_/128, C_/128, B_), 256>>>(pw_w, dw, y, pw_b, out);
}

// round 4
// speedup vs baseline: 1.7978x; 1.4408x over previous
#include <cuda_runtime.h>
#include <cuda_bf16.h>
#include <cstdint>

#define B_  8
#define C_  512
#define H_  32
#define W_  32
#define NH_ 8
#define DH_ 64
#define HW_ 1024
#define C3_ (3*C_)

typedef __nv_bfloat16 bf16;

// ---------------- scratch (device globals; no allocation allowed) ----------
__device__ bf16  g_thi[(size_t)B_*HW_*C_];
__device__ bf16  g_tlo[(size_t)B_*HW_*C_];
__device__ bf16  g_w1hi[(size_t)C3_*C_];
__device__ bf16  g_w1lo[(size_t)C3_*C_];
__device__ bf16  g_w2hi[(size_t)C_*C_];
__device__ bf16  g_w2lo[(size_t)C_*C_];
__device__ bf16  g_w3hi[(size_t)C_*C_];
__device__ bf16  g_w3lo[(size_t)C_*C_];
__device__ float g_qkv[(size_t)B_*HW_*C3_];
__device__ float g_rs [(size_t)B_*NH_*DH_];
__device__ bf16  g_ohi[(size_t)B_*HW_*C_];
__device__ bf16  g_olo[(size_t)B_*HW_*C_];
__device__ float g_ob [(size_t)B_*HW_*C_];
__device__ float g_y  [(size_t)B_*C_*HW_];
__device__ float g_dw [(size_t)B_*C_*HW_];
__device__ bf16  g_dThi[(size_t)B_*HW_*C_];
__device__ bf16  g_dTlo[(size_t)B_*HW_*C_];

// ---------------- small PTX helpers -----------------------------------------
__device__ __forceinline__ uint32_t smem_u32(const void* p) {
    uint32_t a;
    asm("{ .reg .u64 t; cvta.to.shared.u64 t, %1; cvt.u32.u64 %0, t; }"
        : "=r"(a) : "l"(p));
    return a;
}
__device__ __forceinline__ void cp16(uint32_t s, const void* g) {
    asm volatile("cp.async.cg.shared.global [%0], [%1], 16;" :: "r"(s), "l"(g));
}
#define SWZ(x) ((x) ^ (((x) >> 3) & 0x70u))

__device__ __forceinline__ void ldsm4(uint32_t* r, uint32_t addr) {
    asm volatile("ldmatrix.sync.aligned.m8n8.x4.shared.b16 {%0,%1,%2,%3}, [%4];"
                 : "=r"(r[0]), "=r"(r[1]), "=r"(r[2]), "=r"(r[3]) : "r"(addr));
}
__device__ __forceinline__ void mma16816(float* c, const uint32_t* a,
                                         const uint32_t* b) {
    asm volatile(
        "mma.sync.aligned.m16n8k16.row.col.f32.bf16.bf16.f32 "
        "{%0,%1,%2,%3}, {%4,%5,%6,%7}, {%8,%9}, {%0,%1,%2,%3};"
        : "+f"(c[0]), "+f"(c[1]), "+f"(c[2]), "+f"(c[3])
        : "r"(a[0]), "r"(a[1]), "r"(a[2]), "r"(a[3]), "r"(b[0]), "r"(b[1]));
}

// ---------------- HMMA GEMM: D[128,128] = A @ B^T via bf16 hi/lo split ------
// A[M,K], B[N,K] as hi/lo bf16 pairs. C fp32 row-stride Nld (+bias, +resid).
#define GTB   16384u
#define GSMEM (1024 + 8 * 16384)

__device__ __forceinline__ void load_chunk(
    uint32_t dst, int tid, int m0, int n0, int K, int kc,
    const bf16* __restrict__ Ahi, const bf16* __restrict__ Alo,
    const bf16* __restrict__ Bhi, const bf16* __restrict__ Blo) {
#pragma unroll
    for (int it = 0; it < 4; it++) {
        int idx = it * 256 + tid;
        int r = idx >> 3, cg = idx & 7;
        uint32_t so = SWZ((uint32_t)(r * 128 + cg * 16));
        size_t ga = (size_t)(m0 + r) * K + kc + cg * 8;
        size_t gb = (size_t)(n0 + r) * K + kc + cg * 8;
        cp16(dst            + so, Ahi + ga);
        cp16(dst +     GTB  + so, Alo + ga);
        cp16(dst + 2u * GTB + so, Bhi + gb);
        cp16(dst + 3u * GTB + so, Blo + gb);
    }
    asm volatile("cp.async.commit_group;" ::: "memory");
}

__global__ __launch_bounds__(256, 1)
void gemm_tc(const bf16* __restrict__ Ahi, const bf16* __restrict__ Alo,
             const bf16* __restrict__ Bhi, const bf16* __restrict__ Blo,
             const float* __restrict__ bias, const float* __restrict__ resid,
             float* __restrict__ Cout, int K, int Nld,
             long bBatch, long cBatch) {
    extern __shared__ char smc[];
    uint32_t sb = smem_u32(smc);
    int tid = threadIdx.x, wid = tid >> 5, lane = tid & 31;
    int m0 = blockIdx.y * 128, n0 = blockIdx.x * 128;
    Bhi += (size_t)blockIdx.z * bBatch;
    Blo += (size_t)blockIdx.z * bBatch;
    Cout += (size_t)blockIdx.z * cBatch;
    const float* res = resid ? resid + (size_t)blockIdx.z * cBatch : nullptr;

    float* bsm = (float*)smc;
    if (tid < 128) bsm[tid] = bias ? bias[n0 + tid] : 0.f;

    const uint32_t t0 = sb + 1024;
    const int nchunk = K >> 6;
    const int mb = (wid & 3) * 32;   // warp m offset in tile
    const int nb = (wid >> 2) * 64;  // warp n offset in tile

    // per-lane ldmatrix offsets (within a tile, before k-step byte offset)
    const uint32_t aoff = SWZ((uint32_t)((mb + (lane & 15)) * 128 + (lane >> 4) * 16));
    // note: swizzle mixes k-byte offset bits, so recompute per k-step instead:
    float acc[2][8][4];
#pragma unroll
    for (int i = 0; i < 2; i++)
#pragma unroll
        for (int j = 0; j < 8; j++)
#pragma unroll
            for (int q = 0; q < 4; q++) acc[i][j][q] = 0.f;
    (void)aoff;

    load_chunk(t0, tid, m0, n0, K, 0, Ahi, Alo, Bhi, Blo);
    for (int c = 0; c < nchunk; c++) {
        if (c + 1 < nchunk) {
            load_chunk(t0 + (uint32_t)((c + 1) & 1) * (4u * GTB), tid, m0, n0, K,
                       (c + 1) << 6, Ahi, Alo, Bhi, Blo);
            asm volatile("cp.async.wait_group 1;" ::: "memory");
        } else {
            asm volatile("cp.async.wait_group 0;" ::: "memory");
        }
        __syncthreads();
        uint32_t bufA = t0 + (uint32_t)(c & 1) * (4u * GTB);
#pragma unroll
        for (int ks = 0; ks < 4; ks++) {
            int kb = ks * 32;  // byte offset of k16 step (16 bf16 = 32B)
            uint32_t arow = (uint32_t)((mb + (lane & 15)) * 128 +
                                       (lane >> 4) * 16 + kb);
            uint32_t ao = SWZ(arow);
            uint32_t ahi[4], alo[4];
            ldsm4(ahi, bufA + ao);
            ldsm4(alo, bufA + GTB + ao);
            uint32_t brow = (uint32_t)((nb + (lane & 7) + ((lane >> 4) & 1) * 8) * 128 +
                                       ((lane >> 3) & 1) * 16 + kb);
#pragma unroll
            for (int ntp = 0; ntp < 4; ntp++) {
                uint32_t bo = SWZ(brow + (uint32_t)(ntp * 16 * 128));
                uint32_t bhi[4], blo[4];
                ldsm4(bhi, bufA + 2u * GTB + bo);
                ldsm4(blo, bufA + 3u * GTB + bo);
#pragma unroll
                for (int mt = 0; mt < 2; mt++) {
                    uint32_t ah2[4] = {ahi[0], ahi[1], ahi[2], ahi[3]};
                    uint32_t al2[4] = {alo[0], alo[1], alo[2], alo[3]};
                    // A frag for mt=1 uses rows +16: handled by separate ldmatrix
                    (void)ah2; (void)al2;
                }
                // two m16 tiles: need separate A frags for rows mb..mb+15 and +16
                // (loaded below)
                (void)bhi; (void)blo;
                // interleaved mma issued after both A tiles loaded (see below)
                // -- replaced by explicit code:
                {
                    // second A tile fragments
                    uint32_t arow2 = (uint32_t)((mb + 16 + (lane & 15)) * 128 +
                                                (lane >> 4) * 16 + kb);
                    uint32_t ao2 = SWZ(arow2);
                    uint32_t ahi2[4], alo2[4];
                    ldsm4(ahi2, bufA + ao2);
                    ldsm4(alo2, bufA + GTB + ao2);
#pragma unroll
                    for (int half = 0; half < 2; half++) {
                        int nt = ntp * 2 + half;
                        const uint32_t bh[2] = {bhi[half * 2], bhi[half * 2 + 1]};
                        const uint32_t bl[2] = {blo[half * 2], blo[half * 2 + 1]};
                        mma16816(acc[0][nt], ahi, bh);
                        mma16816(acc[0][nt], ahi, bl);
                        mma16816(acc[0][nt], alo, bh);
                        mma16816(acc[1][nt], ahi2, bh);
                        mma16816(acc[1][nt], ahi2, bl);
                        mma16816(acc[1][nt], alo2, bh);
                    }
                }
            }
        }
        __syncthreads();
    }

    // epilogue
    int rbase = m0 + mb + (lane >> 2);
    int cbase = nb + (lane & 3) * 2;
#pragma unroll
    for (int mt = 0; mt < 2; mt++) {
#pragma unroll
        for (int nt = 0; nt < 8; nt++) {
            int ncol = cbase + nt * 8;
            int gcol = n0 + ncol;
            float b0 = bsm[ncol], b1 = bsm[ncol + 1];
#pragma unroll
            for (int rr = 0; rr < 2; rr++) {
                int row = rbase + mt * 16 + rr * 8;
                size_t idx = (size_t)row * Nld + gcol;
                float2 v;
                v.x = acc[mt][nt][rr * 2 + 0] + b0;
                v.y = acc[mt][nt][rr * 2 + 1] + b1;
                if (res) {
                    float2 q = *(const float2*)(res + idx);
                    v.x += q.x; v.y += q.y;
                }
                *(float2*)(Cout + idx) = v;
            }
        }
    }
}

// ---------------- 1) t = transpose(x) + pos -> bf16 hi/lo --------------------
__global__ void build_t_kernel(const float* __restrict__ x,
                               const float* __restrict__ pos,
                               bf16* __restrict__ thi, bf16* __restrict__ tlo) {
    __shared__ float tile[32][33];
    int b  = blockIdx.z;
    int n0 = blockIdx.x * 32;
    int c0 = blockIdx.y * 32;
    int tx = threadIdx.x, ty = threadIdx.y;  // 32 x 8
#pragma unroll
    for (int i = 0; i < 4; i++) {
        int c = c0 + ty + i * 8;
        tile[ty + i * 8][tx] = x[((size_t)b * C_ + c) * HW_ + n0 + tx];
    }
    __syncthreads();
#pragma unroll
    for (int i = 0; i < 4; i++) {
        int n = n0 + ty + i * 8;
        int c = c0 + tx;
        float v = tile[tx][ty + i * 8] + pos[(size_t)n * C_ + c];
        bf16 h = __float2bfloat16(v);
        size_t o = ((size_t)b * HW_ + n) * C_ + c;
        thi[o] = h;
        tlo[o] = __float2bfloat16(v - __bfloat162float(h));
    }
}

// ---------------- weight split ----------------------------------------------
__global__ void split_kernel(const float* __restrict__ w,
                             bf16* __restrict__ hi, bf16* __restrict__ lo, int n) {
    int i = blockIdx.x * 256 + threadIdx.x;
    if (i < n) {
        float v = w[i];
        bf16 h = __float2bfloat16(v);
        hi[i] = h;
        lo[i] = __float2bfloat16(v - __bfloat162float(h));
    }
}

// ---------------- 3) per-(b,h,d) column norms of q,k -> rs ------------------
__global__ void compute_rs_kernel(const float* __restrict__ qkv,
                                  const float* __restrict__ temp,
                                  float* __restrict__ rs) {
    int bh = blockIdx.x;
    int b = bh / NH_, h = bh % NH_;
    int d = threadIdx.x & 63;
    int part = threadIdx.x >> 6;
    float sq = 0.f, sk = 0.f;
    size_t base = (size_t)b * HW_ * C3_ + h * DH_ + d;
    for (int n = part; n < HW_; n += 4) {
        float qv = qkv[base + (size_t)n * C3_];
        float kv = qkv[base + (size_t)n * C3_ + C_];
        sq += qv * qv;
        sk += kv * kv;
    }
    __shared__ float smq[4][64], smk[4][64];
    smq[part][d] = sq; smk[part][d] = sk;
    __syncthreads();
    if (threadIdx.x < 64) {
        float q = smq[0][d] + smq[1][d] + smq[2][d] + smq[3][d];
        float k = smk[0][d] + smk[1][d] + smk[2][d] + smk[3][d];
        float qn = fmaxf(sqrtf(q), 1e-12f);
        float kn = fmaxf(sqrtf(k), 1e-12f);
        rs[(size_t)bh * DH_ + d] = temp[h] / (qn * kn);
    }
}

// ---------------- 4) fused flash attention -> o (bf16 hi/lo) -----------------
#define FA_SMEM ((64*132 + 64*68 + 64*68 + 128*68 + 64) * 4)
__global__ __launch_bounds__(256, 2)
void fused_attn_kernel(const float* __restrict__ qkv,
                       const float* __restrict__ rs,
                       bf16* __restrict__ ohi, bf16* __restrict__ olo) {
    extern __shared__ float sm[];
    float* Qs  = sm;
    float* Ks  = Qs + 64 * 132;
    float* Vs  = Ks + 64 * 68;
    float* Ps  = Vs + 64 * 68;
    float* rss = Ps + 128 * 68;

    int bh = blockIdx.y;
    int b = bh >> 3, h = bh & 7;
    int q0 = blockIdx.x * 128;
    int tid = threadIdx.x;
    int tx = tid & 15, ty = tid >> 4;

    if (tid < 64) rss[tid] = rs[bh * 64 + tid];
    __syncthreads();

#pragma unroll
    for (int v = 0; v < 8; v++) {
        int idx = v * 256 + tid;
        int row = idx >> 4, d = (idx & 15) * 4;
        float4 q = *(const float4*)&qkv[((size_t)(b * HW_ + q0 + row)) * C3_ + h * DH_ + d];
        Qs[(d + 0) * 132 + row] = q.x * rss[d + 0];
        Qs[(d + 1) * 132 + row] = q.y * rss[d + 1];
        Qs[(d + 2) * 132 + row] = q.z * rss[d + 2];
        Qs[(d + 3) * 132 + row] = q.w * rss[d + 3];
    }

    float m[8], l[8], acc[8][4];
#pragma unroll
    for (int i = 0; i < 8; i++) {
        m[i] = -1e30f; l[i] = 0.f;
#pragma unroll
        for (int j = 0; j < 4; j++) acc[i][j] = 0.f;
    }

    for (int kt = 0; kt < 16; kt++) {
        int k0 = kt * 64;
        __syncthreads();
#pragma unroll
        for (int v = 0; v < 4; v++) {
            int idx = v * 256 + tid;
            int row = idx >> 4, d = (idx & 15) * 4;
            size_t base = ((size_t)(b * HW_ + k0 + row)) * C3_ + h * DH_ + d;
            float4 k4 = *(const float4*)&qkv[base + C_];
            Ks[(d + 0) * 68 + row] = k4.x;
            Ks[(d + 1) * 68 + row] = k4.y;
            Ks[(d + 2) * 68 + row] = k4.z;
            Ks[(d + 3) * 68 + row] = k4.w;
            float4 v4 = *(const float4*)&qkv[base + 2 * C_];
            *(float4*)&Vs[row * 68 + d] = v4;
        }
        __syncthreads();

        float s[8][4] = {};
#pragma unroll 8
        for (int kk = 0; kk < 64; kk++) {
            float4 a0 = *(const float4*)&Qs[kk * 132 + ty * 8];
            float4 a1 = *(const float4*)&Qs[kk * 132 + ty * 8 + 4];
            float4 bb = *(const float4*)&Ks[kk * 68 + tx * 4];
            float av[8] = {a0.x, a0.y, a0.z, a0.w, a1.x, a1.y, a1.z, a1.w};
            float bv[4] = {bb.x, bb.y, bb.z, bb.w};
#pragma unroll
            for (int i = 0; i < 8; i++)
#pragma unroll
                for (int j = 0; j < 4; j++) s[i][j] = fmaf(av[i], bv[j], s[i][j]);
        }

#pragma unroll
        for (int i = 0; i < 8; i++) {
            float mx = fmaxf(fmaxf(s[i][0], s[i][1]), fmaxf(s[i][2], s[i][3]));
#pragma unroll
            for (int off = 8; off; off >>= 1)
                mx = fmaxf(mx, __shfl_xor_sync(0xffffffffu, mx, off, 16));
            float mnew = fmaxf(m[i], mx);
            float alpha = __expf(m[i] - mnew);
            float p0 = __expf(s[i][0] - mnew);
            float p1 = __expf(s[i][1] - mnew);
            float p2 = __expf(s[i][2] - mnew);
            float p3 = __expf(s[i][3] - mnew);
            float sum = (p0 + p1) + (p2 + p3);
#pragma unroll
            for (int off = 8; off; off >>= 1)
                sum += __shfl_xor_sync(0xffffffffu, sum, off, 16);
            l[i] = l[i] * alpha + sum;
            m[i] = mnew;
            acc[i][0] *= alpha; acc[i][1] *= alpha;
            acc[i][2] *= alpha; acc[i][3] *= alpha;
            float4 pr; pr.x = p0; pr.y = p1; pr.z = p2; pr.w = p3;
            *(float4*)&Ps[(ty * 8 + i) * 68 + tx * 4] = pr;
        }
        __syncthreads();

#pragma unroll 4
        for (int kk = 0; kk < 64; kk += 4) {
            float4 b0 = *(const float4*)&Vs[(kk + 0) * 68 + tx * 4];
            float4 b1 = *(const float4*)&Vs[(kk + 1) * 68 + tx * 4];
            float4 b2 = *(const float4*)&Vs[(kk + 2) * 68 + tx * 4];
            float4 b3 = *(const float4*)&Vs[(kk + 3) * 68 + tx * 4];
#pragma unroll
            for (int i = 0; i < 8; i++) {
                float4 a4 = *(const float4*)&Ps[(ty * 8 + i) * 68 + kk];
                acc[i][0] = fmaf(a4.x, b0.x, acc[i][0]);
                acc[i][1] = fmaf(a4.x, b0.y, acc[i][1]);
                acc[i][2] = fmaf(a4.x, b0.z, acc[i][2]);
                acc[i][3] = fmaf(a4.x, b0.w, acc[i][3]);
                acc[i][0] = fmaf(a4.y, b1.x, acc[i][0]);
                acc[i][1] = fmaf(a4.y, b1.y, acc[i][1]);
                acc[i][2] = fmaf(a4.y, b1.z, acc[i][2]);
                acc[i][3] = fmaf(a4.y, b1.w, acc[i][3]);
                acc[i][0] = fmaf(a4.z, b2.x, acc[i][0]);
                acc[i][1] = fmaf(a4.z, b2.y, acc[i][1]);
                acc[i][2] = fmaf(a4.z, b2.z, acc[i][2]);
                acc[i][3] = fmaf(a4.z, b2.w, acc[i][3]);
                acc[i][0] = fmaf(a4.w, b3.x, acc[i][0]);
                acc[i][1] = fmaf(a4.w, b3.y, acc[i][1]);
                acc[i][2] = fmaf(a4.w, b3.z, acc[i][2]);
                acc[i][3] = fmaf(a4.w, b3.w, acc[i][3]);
            }
        }
    }

#pragma unroll
    for (int i = 0; i < 8; i++) {
        float inv = 1.f / l[i];
        int n = q0 + ty * 8 + i;
        size_t off = ((size_t)(b * HW_ + n)) * C_ + h * DH_ + tx * 4;
        float v0 = acc[i][0] * inv, v1 = acc[i][1] * inv;
        float v2 = acc[i][2] * inv, v3 = acc[i][3] * inv;
        bf16 h0 = __float2bfloat16(v0), h1 = __float2bfloat16(v1);
        bf16 h2 = __float2bfloat16(v2), h3 = __float2bfloat16(v3);
        __nv_bfloat162 hA; hA.x = h0; hA.y = h1;
        __nv_bfloat162 hB; hB.x = h2; hB.y = h3;
        *(__nv_bfloat162*)&ohi[off]     = hA;
        *(__nv_bfloat162*)&ohi[off + 2] = hB;
        __nv_bfloat162 lA, lB;
        lA.x = __float2bfloat16(v0 - __bfloat162float(h0));
        lA.y = __float2bfloat16(v1 - __bfloat162float(h1));
        lB.x = __float2bfloat16(v2 - __bfloat162float(h2));
        lB.y = __float2bfloat16(v3 - __bfloat162float(h3));
        *(__nv_bfloat162*)&olo[off]     = lA;
        *(__nv_bfloat162*)&olo[off + 2] = lB;
    }
}

// ---------------- LayerNorm over C + residual + transpose to [B,C,HW] -------
__global__ void ln_residual_kernel(const float* __restrict__ ob,
                                   const float* __restrict__ x,
                                   const float* __restrict__ g,
                                   const float* __restrict__ be,
                                   float* __restrict__ y) {
    int row = blockIdx.x;
    int b = row >> 10, n = row & 1023;
    const float* pr = ob + (size_t)row * C_;
    int tid = threadIdx.x;
    float v0 = pr[tid], v1 = pr[tid + 256];
    __shared__ float red[256];
    red[tid] = v0 + v1; __syncthreads();
    for (int s = 128; s > 0; s >>= 1) {
        if (tid < s) red[tid] += red[tid + s];
        __syncthreads();
    }
    float mean = red[0] * (1.0f / C_);
    __syncthreads();
    float d0 = v0 - mean, d1 = v1 - mean;
    red[tid] = d0 * d0 + d1 * d1; __syncthreads();
    for (int s = 128; s > 0; s >>= 1) {
        if (tid < s) red[tid] += red[tid + s];
        __syncthreads();
    }
    float rstd = rsqrtf(red[0] * (1.0f / C_) + 1e-5f);
    int c0 = tid, c1 = tid + 256;
    size_t i0 = ((size_t)b * C_ + c0) * HW_ + n;
    size_t i1 = ((size_t)b * C_ + c1) * HW_ + n;
    y[i0] = d0 * rstd * g[c0] + be[c0] + x[i0];
    y[i1] = d1 * rstd * g[c1] + be[c1] + x[i1];
}

// ---------------- depthwise 3x3 SAME -----------------------------------------
__global__ void dwconv_kernel(const float* __restrict__ y,
                              const float* __restrict__ w,
                              const float* __restrict__ bias,
                              float* __restrict__ out) {
    int bc = blockIdx.x;
    int c = bc % C_;
    int hw = blockIdx.y * 256 + threadIdx.x;
    int hh = hw >> 5, ww = hw & 31;
    const float* p = y + (size_t)bc * HW_;
    float acc = bias[c];
#pragma unroll
    for (int ki = 0; ki < 3; ki++) {
        int ih = hh + ki - 1;
        if (ih < 0 || ih >= H_) continue;
#pragma unroll
        for (int kj = 0; kj < 3; kj++) {
            int iw = ww + kj - 1;
            if (iw < 0 || iw >= W_) continue;
            acc += w[c * 9 + ki * 3 + kj] * p[ih * W_ + iw];
        }
    }
    out[(size_t)bc * HW_ + hw] = acc;
}

// ---------------- dw [b][c][hw] -> dwT hi/lo [b][hw][c] ----------------------
__global__ void transpose_split_kernel(const float* __restrict__ src,
                                       bf16* __restrict__ hi, bf16* __restrict__ lo) {
    __shared__ float tile[32][33];
    int b = blockIdx.z, n0 = blockIdx.x * 32, c0 = blockIdx.y * 32;
    int tx = threadIdx.x, ty = threadIdx.y;  // 32 x 8
#pragma unroll
    for (int i = 0; i < 4; i++) {
        int c = c0 + ty + i * 8;
        tile[ty + i * 8][tx] = src[((size_t)b * C_ + c) * HW_ + n0 + tx];
    }
    __syncthreads();
#pragma unroll
    for (int i = 0; i < 4; i++) {
        int n = n0 + ty + i * 8;
        int c = c0 + tx;
        float v = tile[tx][ty + i * 8];
        bf16 h = __float2bfloat16(v);
        size_t o = ((size_t)b * HW_ + n) * C_ + c;
        hi[o] = h;
        lo[o] = __float2bfloat16(v - __bfloat162float(h));
    }
}

// ---------------- launch ------------------------------------------------------
extern "C" void kernel_launch(void* const* d_in, const int* in_sizes, int n_in,
                              void* d_out, int out_size) {
    const float* x      = (const float*)d_in[0];
    const float* qkv_w  = (const float*)d_in[1];
    const float* proj_w = (const float*)d_in[2];
    const float* proj_b = (const float*)d_in[3];
    const float* temper = (const float*)d_in[4];
    const float* ln_g   = (const float*)d_in[5];
    const float* ln_b   = (const float*)d_in[6];
    const float* pos    = (const float*)d_in[7];
    const float* dw_w   = (const float*)d_in[8];
    const float* dw_b   = (const float*)d_in[9];
    const float* pw_w   = (const float*)d_in[10];
    const float* pw_b   = (const float*)d_in[11];
    float* out = (float*)d_out;

    bf16 *thi, *tlo, *w1hi, *w1lo, *w2hi, *w2lo, *w3hi, *w3lo;
    bf16 *ohi, *olo, *dThi, *dTlo;
    float *qkv, *rs, *ob, *y, *dw;
    cudaGetSymbolAddress((void**)&thi,  g_thi);
    cudaGetSymbolAddress((void**)&tlo,  g_tlo);
    cudaGetSymbolAddress((void**)&w1hi, g_w1hi);
    cudaGetSymbolAddress((void**)&w1lo, g_w1lo);
    cudaGetSymbolAddress((void**)&w2hi, g_w2hi);
    cudaGetSymbolAddress((void**)&w2lo, g_w2lo);
    cudaGetSymbolAddress((void**)&w3hi, g_w3hi);
    cudaGetSymbolAddress((void**)&w3lo, g_w3lo);
    cudaGetSymbolAddress((void**)&ohi,  g_ohi);
    cudaGetSymbolAddress((void**)&olo,  g_olo);
    cudaGetSymbolAddress((void**)&dThi, g_dThi);
    cudaGetSymbolAddress((void**)&dTlo, g_dTlo);
    cudaGetSymbolAddress((void**)&qkv,  g_qkv);
    cudaGetSymbolAddress((void**)&rs,   g_rs);
    cudaGetSymbolAddress((void**)&ob,   g_ob);
    cudaGetSymbolAddress((void**)&y,    g_y);
    cudaGetSymbolAddress((void**)&dw,   g_dw);

    cudaFuncSetAttribute(fused_attn_kernel,
                         cudaFuncAttributeMaxDynamicSharedMemorySize, FA_SMEM);
    cudaFuncSetAttribute(gemm_tc,
                         cudaFuncAttributeMaxDynamicSharedMemorySize, GSMEM);

    // weight splits
    split_kernel<<<(C3_*C_ + 255)/256, 256>>>(qkv_w, w1hi, w1lo, C3_*C_);
    split_kernel<<<(C_*C_  + 255)/256, 256>>>(proj_w, w2hi, w2lo, C_*C_);
    split_kernel<<<(C_*C_  + 255)/256, 256>>>(pw_w,  w3hi, w3lo, C_*C_);
    // t = transpose(x) + pos (bf16 split)
    build_t_kernel<<<dim3(HW_/32, C_/32, B_), dim3(32, 8)>>>(x, pos, thi, tlo);
    // qkv = t @ qkv_w^T  (tensor cores via mma.sync)
    gemm_tc<<<dim3(C3_/128, (B_*HW_)/128, 1), 256, GSMEM>>>(
        thi, tlo, w1hi, w1lo, nullptr, nullptr, qkv, C_, C3_, 0, 0);
    // column-norm scales
    compute_rs_kernel<<<B_*NH_, 256>>>(qkv, temper, rs);
    // fused attention -> o (bf16 split)
    fused_attn_kernel<<<dim3(HW_/128, B_*NH_), 256, FA_SMEM>>>(qkv, rs, ohi, olo);
    // proj = o @ proj_w^T + proj_b
    gemm_tc<<<dim3(C_/128, (B_*HW_)/128, 1), 256, GSMEM>>>(
        ohi, olo, w2hi, w2lo, proj_b, nullptr, ob, C_, C_, 0, 0);
    // LN + residual + transpose to [B,C,HW]
    ln_residual_kernel<<<B_*HW_, 256>>>(ob, x, ln_g, ln_b, y);
    // depthwise 3x3
    dwconv_kernel<<<dim3(B_*C_, HW_/256), 256>>>(y, dw_w, dw_b, dw);
    // transpose dw to [b][hw][c] bf16 split
    transpose_split_kernel<<<dim3(HW_/32, C_/32, B_), dim3(32, 8)>>>(dw, dThi, dTlo);
    // pointwise: out[b][c][hw] = pw_w @ dwT^T + pw_b + y
    gemm_tc<<<dim3(HW_/128, C_/128, B_), 256, GSMEM>>>(
        w3hi, w3lo, dThi, dTlo, pw_b, y, out, C_, HW_,
        (long)HW_*C_, (long)C_*HW_);
}

// round 5
// speedup vs baseline: 2.8550x; 1.5881x over previous
#include <cuda_runtime.h>
#include <cuda_bf16.h>
#include <cstdint>

#define B_  8
#define C_  512
#define H_  32
#define W_  32
#define NH_ 8
#define DH_ 64
#define HW_ 1024
#define C3_ (3*C_)

typedef __nv_bfloat16 bf16;

// ---------------- scratch (device globals; no allocation allowed) ----------
__device__ bf16  g_thi[(size_t)B_*HW_*C_];
__device__ bf16  g_tlo[(size_t)B_*HW_*C_];
__device__ bf16  g_w1hi[(size_t)C3_*C_];
__device__ bf16  g_w1lo[(size_t)C3_*C_];
__device__ bf16  g_w2hi[(size_t)C_*C_];
__device__ bf16  g_w2lo[(size_t)C_*C_];
__device__ bf16  g_w3hi[(size_t)C_*C_];
__device__ bf16  g_w3lo[(size_t)C_*C_];
__device__ float g_qkv[(size_t)B_*HW_*C3_];
__device__ float g_rs [(size_t)B_*NH_*DH_];
__device__ bf16  g_khi[(size_t)B_*NH_*HW_*DH_];
__device__ bf16  g_klo[(size_t)B_*NH_*HW_*DH_];
__device__ bf16  g_vhi[(size_t)B_*NH_*HW_*DH_];
__device__ bf16  g_vlo[(size_t)B_*NH_*HW_*DH_];
__device__ bf16  g_ohi[(size_t)B_*HW_*C_];
__device__ bf16  g_olo[(size_t)B_*HW_*C_];
__device__ float g_ob [(size_t)B_*HW_*C_];
__device__ float g_y  [(size_t)B_*C_*HW_];
__device__ float g_dw [(size_t)B_*C_*HW_];
__device__ bf16  g_dThi[(size_t)B_*HW_*C_];
__device__ bf16  g_dTlo[(size_t)B_*HW_*C_];

// ---------------- small PTX helpers -----------------------------------------
__device__ __forceinline__ uint32_t smem_u32(const void* p) {
    uint32_t a;
    asm("{ .reg .u64 t; cvta.to.shared.u64 t, %1; cvt.u32.u64 %0, t; }"
        : "=r"(a) : "l"(p));
    return a;
}
__device__ __forceinline__ void cp16(uint32_t s, const void* g) {
    asm volatile("cp.async.cg.shared.global [%0], [%1], 16;" :: "r"(s), "l"(g));
}
#define SWZ(x) ((x) ^ (((x) >> 3) & 0x70u))

__device__ __forceinline__ void ldsm4(uint32_t* r, uint32_t addr) {
    asm volatile("ldmatrix.sync.aligned.m8n8.x4.shared.b16 {%0,%1,%2,%3}, [%4];"
                 : "=r"(r[0]), "=r"(r[1]), "=r"(r[2]), "=r"(r[3]) : "r"(addr));
}
__device__ __forceinline__ void ldsm4t(uint32_t* r, uint32_t addr) {
    asm volatile("ldmatrix.sync.aligned.m8n8.x4.trans.shared.b16 {%0,%1,%2,%3}, [%4];"
                 : "=r"(r[0]), "=r"(r[1]), "=r"(r[2]), "=r"(r[3]) : "r"(addr));
}
__device__ __forceinline__ void mma16816(float* c, const uint32_t* a,
                                         const uint32_t* b) {
    asm volatile(
        "mma.sync.aligned.m16n8k16.row.col.f32.bf16.bf16.f32 "
        "{%0,%1,%2,%3}, {%4,%5,%6,%7}, {%8,%9}, {%0,%1,%2,%3};"
        : "+f"(c[0]), "+f"(c[1]), "+f"(c[2]), "+f"(c[3])
        : "r"(a[0]), "r"(a[1]), "r"(a[2]), "r"(a[3]), "r"(b[0]), "r"(b[1]));
}
__device__ __forceinline__ void split2(float a, float b, uint32_t& hi, uint32_t& lo) {
    __nv_bfloat16 ha = __float2bfloat16(a), hb = __float2bfloat16(b);
    __nv_bfloat162 h; h.x = ha; h.y = hb;
    hi = *(uint32_t*)&h;
    __nv_bfloat162 l;
    l.x = __float2bfloat16(a - __bfloat162float(ha));
    l.y = __float2bfloat16(b - __bfloat162float(hb));
    lo = *(uint32_t*)&l;
}

// ---------------- HMMA GEMM: D[128,128] = A @ B^T via bf16 hi/lo split ------
#define GTB   16384u
#define GSMEM (1024 + 8 * 16384)

__device__ __forceinline__ void load_chunk(
    uint32_t dst, int tid, int m0, int n0, int K, int kc,
    const bf16* __restrict__ Ahi, const bf16* __restrict__ Alo,
    const bf16* __restrict__ Bhi, const bf16* __restrict__ Blo) {
#pragma unroll
    for (int it = 0; it < 4; it++) {
        int idx = it * 256 + tid;
        int r = idx >> 3, cg = idx & 7;
        uint32_t so = SWZ((uint32_t)(r * 128 + cg * 16));
        size_t ga = (size_t)(m0 + r) * K + kc + cg * 8;
        size_t gb = (size_t)(n0 + r) * K + kc + cg * 8;
        cp16(dst            + so, Ahi + ga);
        cp16(dst +     GTB  + so, Alo + ga);
        cp16(dst + 2u * GTB + so, Bhi + gb);
        cp16(dst + 3u * GTB + so, Blo + gb);
    }
    asm volatile("cp.async.commit_group;" ::: "memory");
}

__global__ __launch_bounds__(256, 1)
void gemm_tc(const bf16* __restrict__ Ahi, const bf16* __restrict__ Alo,
             const bf16* __restrict__ Bhi, const bf16* __restrict__ Blo,
             const float* __restrict__ bias, const float* __restrict__ resid,
             float* __restrict__ Cout, int K, int Nld,
             long bBatch, long cBatch) {
    extern __shared__ char smc[];
    uint32_t sb = smem_u32(smc);
    int tid = threadIdx.x, wid = tid >> 5, lane = tid & 31;
    int m0 = blockIdx.y * 128, n0 = blockIdx.x * 128;
    Bhi += (size_t)blockIdx.z * bBatch;
    Blo += (size_t)blockIdx.z * bBatch;
    Cout += (size_t)blockIdx.z * cBatch;
    const float* res = resid ? resid + (size_t)blockIdx.z * cBatch : nullptr;

    float* bsm = (float*)smc;
    if (tid < 128) bsm[tid] = bias ? bias[n0 + tid] : 0.f;

    const uint32_t t0 = sb + 1024;
    const int nchunk = K >> 6;
    const int mb = (wid & 3) * 32;
    const int nb = (wid >> 2) * 64;

    float acc[2][8][4];
#pragma unroll
    for (int i = 0; i < 2; i++)
#pragma unroll
        for (int j = 0; j < 8; j++)
#pragma unroll
            for (int q = 0; q < 4; q++) acc[i][j][q] = 0.f;

    load_chunk(t0, tid, m0, n0, K, 0, Ahi, Alo, Bhi, Blo);
    for (int c = 0; c < nchunk; c++) {
        if (c + 1 < nchunk) {
            load_chunk(t0 + (uint32_t)((c + 1) & 1) * (4u * GTB), tid, m0, n0, K,
                       (c + 1) << 6, Ahi, Alo, Bhi, Blo);
            asm volatile("cp.async.wait_group 1;" ::: "memory");
        } else {
            asm volatile("cp.async.wait_group 0;" ::: "memory");
        }
        __syncthreads();
        uint32_t bufA = t0 + (uint32_t)(c & 1) * (4u * GTB);
#pragma unroll
        for (int ks = 0; ks < 4; ks++) {
            int kb = ks * 32;
            uint32_t ao = SWZ((uint32_t)((mb + (lane & 15)) * 128 +
                                         (lane >> 4) * 16 + kb));
            uint32_t ahi[4], alo[4];
            ldsm4(ahi, bufA + ao);
            ldsm4(alo, bufA + GTB + ao);
            uint32_t ao2 = SWZ((uint32_t)((mb + 16 + (lane & 15)) * 128 +
                                          (lane >> 4) * 16 + kb));
            uint32_t ahi2[4], alo2[4];
            ldsm4(ahi2, bufA + ao2);
            ldsm4(alo2, bufA + GTB + ao2);
            uint32_t brow = (uint32_t)((nb + (lane & 7) + ((lane >> 4) & 1) * 8) * 128 +
                                       ((lane >> 3) & 1) * 16 + kb);
#pragma unroll
            for (int ntp = 0; ntp < 4; ntp++) {
                uint32_t bo = SWZ(brow + (uint32_t)(ntp * 16 * 128));
                uint32_t bhi[4], blo[4];
                ldsm4(bhi, bufA + 2u * GTB + bo);
                ldsm4(blo, bufA + 3u * GTB + bo);
#pragma unroll
                for (int half = 0; half < 2; half++) {
                    int nt = ntp * 2 + half;
                    const uint32_t bh[2] = {bhi[half * 2], bhi[half * 2 + 1]};
                    const uint32_t bl[2] = {blo[half * 2], blo[half * 2 + 1]};
                    mma16816(acc[0][nt], ahi, bh);
                    mma16816(acc[0][nt], ahi, bl);
                    mma16816(acc[0][nt], alo, bh);
                    mma16816(acc[1][nt], ahi2, bh);
                    mma16816(acc[1][nt], ahi2, bl);
                    mma16816(acc[1][nt], alo2, bh);
                }
            }
        }
        __syncthreads();
    }

    int rbase = m0 + mb + (lane >> 2);
    int cbase = nb + (lane & 3) * 2;
#pragma unroll
    for (int mt = 0; mt < 2; mt++) {
#pragma unroll
        for (int nt = 0; nt < 8; nt++) {
            int ncol = cbase + nt * 8;
            int gcol = n0 + ncol;
            float b0 = bsm[ncol], b1 = bsm[ncol + 1];
#pragma unroll
            for (int rr = 0; rr < 2; rr++) {
                int row = rbase + mt * 16 + rr * 8;
                size_t idx = (size_t)row * Nld + gcol;
                float2 v;
                v.x = acc[mt][nt][rr * 2 + 0] + b0;
                v.y = acc[mt][nt][rr * 2 + 1] + b1;
                if (res) {
                    float2 q = *(const float2*)(res + idx);
                    v.x += q.x; v.y += q.y;
                }
                *(float2*)(Cout + idx) = v;
            }
        }
    }
}

// ---------------- 1) t = transpose(x) + pos -> bf16 hi/lo --------------------
__global__ void build_t_kernel(const float* __restrict__ x,
                               const float* __restrict__ pos,
                               bf16* __restrict__ thi, bf16* __restrict__ tlo) {
    __shared__ float tile[32][33];
    int b  = blockIdx.z;
    int n0 = blockIdx.x * 32;
    int c0 = blockIdx.y * 32;
    int tx = threadIdx.x, ty = threadIdx.y;
#pragma unroll
    for (int i = 0; i < 4; i++) {
        int c = c0 + ty + i * 8;
        tile[ty + i * 8][tx] = x[((size_t)b * C_ + c) * HW_ + n0 + tx];
    }
    __syncthreads();
#pragma unroll
    for (int i = 0; i < 4; i++) {
        int n = n0 + ty + i * 8;
        int c = c0 + tx;
        float v = tile[tx][ty + i * 8] + pos[(size_t)n * C_ + c];
        bf16 h = __float2bfloat16(v);
        size_t o = ((size_t)b * HW_ + n) * C_ + c;
        thi[o] = h;
        tlo[o] = __float2bfloat16(v - __bfloat162float(h));
    }
}

// ---------------- weight split ----------------------------------------------
__global__ void split_kernel(const float* __restrict__ w,
                             bf16* __restrict__ hi, bf16* __restrict__ lo, int n) {
    int i = blockIdx.x * 256 + threadIdx.x;
    if (i < n) {
        float v = w[i];
        bf16 h = __float2bfloat16(v);
        hi[i] = h;
        lo[i] = __float2bfloat16(v - __bfloat162float(h));
    }
}

// ---------------- K/V reshape + split: qkv -> [bh][n][64] hi/lo --------------
__global__ void kvsplit_kernel(const float* __restrict__ qkv,
                               bf16* __restrict__ khi, bf16* __restrict__ klo,
                               bf16* __restrict__ vhi, bf16* __restrict__ vlo) {
    int gid = blockIdx.x * 256 + threadIdx.x;   // B*NH*HW*16
    int d4 = gid & 15;
    int n  = (gid >> 4) & (HW_ - 1);
    int bh = gid >> 14;
    int b = bh >> 3, h = bh & 7;
    size_t src = ((size_t)(b * HW_ + n)) * C3_ + C_ + h * DH_ + d4 * 4;
    float4 k4 = *(const float4*)&qkv[src];
    float4 v4 = *(const float4*)&qkv[src + C_];
    size_t dst = ((size_t)bh * HW_ + n) * DH_ + d4 * 4;
    uint32_t h0, l0, h1, l1;
    split2(k4.x, k4.y, h0, l0); split2(k4.z, k4.w, h1, l1);
    *(uint32_t*)&khi[dst] = h0; *(uint32_t*)&khi[dst + 2] = h1;
    *(uint32_t*)&klo[dst] = l0; *(uint32_t*)&klo[dst + 2] = l1;
    split2(v4.x, v4.y, h0, l0); split2(v4.z, v4.w, h1, l1);
    *(uint32_t*)&vhi[dst] = h0; *(uint32_t*)&vhi[dst + 2] = h1;
    *(uint32_t*)&vlo[dst] = l0; *(uint32_t*)&vlo[dst + 2] = l1;
}

// ---------------- 3) per-(b,h,d) column norms of q,k -> rs ------------------
__global__ void compute_rs_kernel(const float* __restrict__ qkv,
                                  const float* __restrict__ temp,
                                  float* __restrict__ rs) {
    int bh = blockIdx.x;
    int b = bh / NH_, h = bh % NH_;
    int d = threadIdx.x & 63;
    int part = threadIdx.x >> 6;
    float sq = 0.f, sk = 0.f;
    size_t base = (size_t)b * HW_ * C3_ + h * DH_ + d;
    for (int n = part; n < HW_; n += 4) {
        float qv = qkv[base + (size_t)n * C3_];
        float kv = qkv[base + (size_t)n * C3_ + C_];
        sq += qv * qv;
        sk += kv * kv;
    }
    __shared__ float smq[4][64], smk[4][64];
    smq[part][d] = sq; smk[part][d] = sk;
    __syncthreads();
    if (threadIdx.x < 64) {
        float q = smq[0][d] + smq[1][d] + smq[2][d] + smq[3][d];
        float k = smk[0][d] + smk[1][d] + smk[2][d] + smk[3][d];
        float qn = fmaxf(sqrtf(q), 1e-12f);
        float kn = fmaxf(sqrtf(k), 1e-12f);
        rs[(size_t)bh * DH_ + d] = temp[h] / (qn * kn);
    }
}

// ---------------- 4) tensor-core fused flash attention -----------------------
// Per block: (bh, 128 q rows). 8 warps x 16 rows. S and O via mma.sync bf16
// hi/lo 3-term split; online softmax in registers (FA2 fragment layout).
#define FAT_SMEM (65536 + 256)

__device__ __forceinline__ void fat_loadkv(
    uint32_t buf, int tid, size_t kvbase, int kc,
    const bf16* __restrict__ khi, const bf16* __restrict__ klo,
    const bf16* __restrict__ vhi, const bf16* __restrict__ vlo) {
#pragma unroll
    for (int it = 0; it < 2; it++) {
        int idx = it * 256 + tid;
        int r = idx >> 3, cg = idx & 7;
        uint32_t so = SWZ((uint32_t)(r * 128 + cg * 16));
        size_t g = kvbase + (size_t)(kc + r) * DH_ + cg * 8;
        cp16(buf +     0u + so, khi + g);
        cp16(buf +  8192u + so, klo + g);
        cp16(buf + 16384u + so, vhi + g);
        cp16(buf + 24576u + so, vlo + g);
    }
    asm volatile("cp.async.commit_group;" ::: "memory");
}

__global__ __launch_bounds__(256, 1)
void fat_kernel(const float* __restrict__ qkv, const float* __restrict__ rs,
                const bf16* __restrict__ khi, const bf16* __restrict__ klo,
                const bf16* __restrict__ vhi, const bf16* __restrict__ vlo,
                bf16* __restrict__ ohi, bf16* __restrict__ olo) {
    extern __shared__ char smc[];
    uint32_t sb = smem_u32(smc);
    float* rss = (float*)(smc + 65536);
    int bh = blockIdx.y;
    int b = bh >> 3, h = bh & 7;
    int q0 = blockIdx.x * 128;
    int tid = threadIdx.x, wid = tid >> 5, lane = tid & 31;
    int mb = wid * 16;

    if (tid < 64) rss[tid] = rs[bh * DH_ + tid];
    __syncthreads();

    // stage Q (scaled by rs) hi/lo into smem buffer0
#pragma unroll
    for (int v = 0; v < 8; v++) {
        int idx = v * 256 + tid;
        int row = idx >> 4, dq = (idx & 15) * 4;
        float4 q = *(const float4*)&qkv[((size_t)(b * HW_ + q0 + row)) * C3_ +
                                        h * DH_ + dq];
        q.x *= rss[dq]; q.y *= rss[dq + 1]; q.z *= rss[dq + 2]; q.w *= rss[dq + 3];
        uint32_t h0, l0, h1, l1;
        split2(q.x, q.y, h0, l0);
        split2(q.z, q.w, h1, l1);
        uint32_t off = SWZ((uint32_t)(row * 128 + dq * 2));
        *(uint32_t*)(smc + off)             = h0;
        *(uint32_t*)(smc + off + 4)         = h1;
        *(uint32_t*)(smc + 16384 + off)     = l0;
        *(uint32_t*)(smc + 16384 + off + 4) = l1;
    }
    __syncthreads();

    // Q fragments to registers
    uint32_t qh[4][4], ql[4][4];
#pragma unroll
    for (int ks = 0; ks < 4; ks++) {
        uint32_t ao = SWZ((uint32_t)((mb + (lane & 15)) * 128 +
                                     (lane >> 4) * 16 + ks * 32));
        ldsm4(qh[ks], sb + ao);
        ldsm4(ql[ks], sb + 16384 + ao);
    }
    __syncthreads();

    float o[8][4];
#pragma unroll
    for (int j = 0; j < 8; j++)
#pragma unroll
        for (int q = 0; q < 4; q++) o[j][q] = 0.f;
    float m0 = -1e30f, m1 = -1e30f, l0 = 0.f, l1 = 0.f;
    const size_t kvbase = (size_t)bh * HW_ * DH_;

    fat_loadkv(sb, tid, kvbase, 0, khi, klo, vhi, vlo);
    for (int kt = 0; kt < 16; kt++) {
        uint32_t cur = sb + (uint32_t)(kt & 1) * 32768u;
        if (kt + 1 < 16) {
            fat_loadkv(sb + (uint32_t)((kt + 1) & 1) * 32768u, tid, kvbase,
                       (kt + 1) * 64, khi, klo, vhi, vlo);
            asm volatile("cp.async.wait_group 1;" ::: "memory");
        } else {
            asm volatile("cp.async.wait_group 0;" ::: "memory");
        }
        __syncthreads();

        // ---- S = Q.K^T (3-term split)
        float s[8][4];
#pragma unroll
        for (int j = 0; j < 8; j++)
#pragma unroll
            for (int q = 0; q < 4; q++) s[j][q] = 0.f;
#pragma unroll
        for (int ks = 0; ks < 4; ks++) {
            uint32_t brow = (uint32_t)(((lane & 7) + ((lane >> 4) & 1) * 8) * 128 +
                                       ((lane >> 3) & 1) * 16 + ks * 32);
#pragma unroll
            for (int np = 0; np < 4; np++) {
                uint32_t bo = SWZ(brow + (uint32_t)(np * 16 * 128));
                uint32_t kh4[4], kl4[4];
                ldsm4(kh4, cur + bo);
                ldsm4(kl4, cur + 8192u + bo);
#pragma unroll
                for (int half = 0; half < 2; half++) {
                    int j = np * 2 + half;
                    const uint32_t bhh[2] = {kh4[half * 2], kh4[half * 2 + 1]};
                    const uint32_t bll[2] = {kl4[half * 2], kl4[half * 2 + 1]};
                    mma16816(s[j], qh[ks], bhh);
                    mma16816(s[j], qh[ks], bll);
                    mma16816(s[j], ql[ks], bhh);
                }
            }
        }

        // ---- online softmax (rows r=lane>>2 and r+8; quads share rows)
        float mx0 = -1e30f, mx1 = -1e30f;
#pragma unroll
        for (int j = 0; j < 8; j++) {
            mx0 = fmaxf(mx0, fmaxf(s[j][0], s[j][1]));
            mx1 = fmaxf(mx1, fmaxf(s[j][2], s[j][3]));
        }
        mx0 = fmaxf(mx0, __shfl_xor_sync(0xffffffffu, mx0, 1));
        mx0 = fmaxf(mx0, __shfl_xor_sync(0xffffffffu, mx0, 2));
        mx1 = fmaxf(mx1, __shfl_xor_sync(0xffffffffu, mx1, 1));
        mx1 = fmaxf(mx1, __shfl_xor_sync(0xffffffffu, mx1, 2));
        float mn0 = fmaxf(m0, mx0), mn1 = fmaxf(m1, mx1);
        float al0 = __expf(m0 - mn0), al1 = __expf(m1 - mn1);
        float sum0 = 0.f, sum1 = 0.f;
#pragma unroll
        for (int j = 0; j < 8; j++) {
            s[j][0] = __expf(s[j][0] - mn0);
            s[j][1] = __expf(s[j][1] - mn0);
            s[j][2] = __expf(s[j][2] - mn1);
            s[j][3] = __expf(s[j][3] - mn1);
            sum0 += s[j][0] + s[j][1];
            sum1 += s[j][2] + s[j][3];
        }
        sum0 += __shfl_xor_sync(0xffffffffu, sum0, 1);
        sum0 += __shfl_xor_sync(0xffffffffu, sum0, 2);
        sum1 += __shfl_xor_sync(0xffffffffu, sum1, 1);
        sum1 += __shfl_xor_sync(0xffffffffu, sum1, 2);
        l0 = l0 * al0 + sum0; l1 = l1 * al1 + sum1;
        m0 = mn0; m1 = mn1;
#pragma unroll
        for (int j = 0; j < 8; j++) {
            o[j][0] *= al0; o[j][1] *= al0;
            o[j][2] *= al1; o[j][3] *= al1;
        }

        // ---- O += P.V (3-term split); P frags packed straight from S frags
#pragma unroll
        for (int ks = 0; ks < 4; ks++) {
            int j0 = 2 * ks, j1 = 2 * ks + 1;
            uint32_t ph[4], pl[4];
            split2(s[j0][0], s[j0][1], ph[0], pl[0]);
            split2(s[j0][2], s[j0][3], ph[1], pl[1]);
            split2(s[j1][0], s[j1][1], ph[2], pl[2]);
            split2(s[j1][2], s[j1][3], ph[3], pl[3]);
            uint32_t vrow = (uint32_t)((ks * 16 + (lane & 7) + ((lane >> 3) & 1) * 8) * 128 +
                                       ((lane >> 4) & 1) * 16);
#pragma unroll
            for (int np = 0; np < 4; np++) {
                uint32_t vo = SWZ(vrow + (uint32_t)(np * 32));
                uint32_t vh4[4], vl4[4];
                ldsm4t(vh4, cur + 16384u + vo);
                ldsm4t(vl4, cur + 24576u + vo);
#pragma unroll
                for (int half = 0; half < 2; half++) {
                    int j = np * 2 + half;
                    const uint32_t bvh[2] = {vh4[half * 2], vh4[half * 2 + 1]};
                    const uint32_t bvl[2] = {vl4[half * 2], vl4[half * 2 + 1]};
                    mma16816(o[j], ph, bvh);
                    mma16816(o[j], ph, bvl);
                    mma16816(o[j], pl, bvh);
                }
            }
        }
        __syncthreads();
    }

    // epilogue: normalize, split, store
    float inv0 = 1.f / l0, inv1 = 1.f / l1;
    int r0 = lane >> 2, cc = (lane & 3) * 2;
    int row0 = q0 + mb + r0, row1 = row0 + 8;
#pragma unroll
    for (int j = 0; j < 8; j++) {
        int col = h * DH_ + j * 8 + cc;
        size_t off0 = ((size_t)(b * HW_ + row0)) * C_ + col;
        size_t off1 = ((size_t)(b * HW_ + row1)) * C_ + col;
        uint32_t hi, lo;
        split2(o[j][0] * inv0, o[j][1] * inv0, hi, lo);
        *(uint32_t*)&ohi[off0] = hi; *(uint32_t*)&olo[off0] = lo;
        split2(o[j][2] * inv1, o[j][3] * inv1, hi, lo);
        *(uint32_t*)&ohi[off1] = hi; *(uint32_t*)&olo[off1] = lo;
    }
}

// ---------------- LayerNorm over C + residual + transpose to [B,C,HW] -------
__global__ void ln_residual_kernel(const float* __restrict__ ob,
                                   const float* __restrict__ x,
                                   const float* __restrict__ g,
                                   const float* __restrict__ be,
                                   float* __restrict__ y) {
    int row = blockIdx.x;
    int b = row >> 10, n = row & 1023;
    const float* pr = ob + (size_t)row * C_;
    int tid = threadIdx.x;
    float v0 = pr[tid], v1 = pr[tid + 256];
    __shared__ float red[256];
    red[tid] = v0 + v1; __syncthreads();
    for (int s = 128; s > 0; s >>= 1) {
        if (tid < s) red[tid] += red[tid + s];
        __syncthreads();
    }
    float mean = red[0] * (1.0f / C_);
    __syncthreads();
    float d0 = v0 - mean, d1 = v1 - mean;
    red[tid] = d0 * d0 + d1 * d1; __syncthreads();
    for (int s = 128; s > 0; s >>= 1) {
        if (tid < s) red[tid] += red[tid + s];
        __syncthreads();
    }
    float rstd = rsqrtf(red[0] * (1.0f / C_) + 1e-5f);
    int c0 = tid, c1 = tid + 256;
    size_t i0 = ((size_t)b * C_ + c0) * HW_ + n;
    size_t i1 = ((size_t)b * C_ + c1) * HW_ + n;
    y[i0] = d0 * rstd * g[c0] + be[c0] + x[i0];
    y[i1] = d1 * rstd * g[c1] + be[c1] + x[i1];
}

// ---------------- depthwise 3x3 SAME -----------------------------------------
__global__ void dwconv_kernel(const float* __restrict__ y,
                              const float* __restrict__ w,
                              const float* __restrict__ bias,
                              float* __restrict__ out) {
    int bc = blockIdx.x;
    int c = bc % C_;
    int hw = blockIdx.y * 256 + threadIdx.x;
    int hh = hw >> 5, ww = hw & 31;
    const float* p = y + (size_t)bc * HW_;
    float acc = bias[c];
#pragma unroll
    for (int ki = 0; ki < 3; ki++) {
        int ih = hh + ki - 1;
        if (ih < 0 || ih >= H_) continue;
#pragma unroll
        for (int kj = 0; kj < 3; kj++) {
            int iw = ww + kj - 1;
            if (iw < 0 || iw >= W_) continue;
            acc += w[c * 9 + ki * 3 + kj] * p[ih * W_ + iw];
        }
    }
    out[(size_t)bc * HW_ + hw] = acc;
}

// ---------------- dw [b][c][hw] -> dwT hi/lo [b][hw][c] ----------------------
__global__ void transpose_split_kernel(const float* __restrict__ src,
                                       bf16* __restrict__ hi, bf16* __restrict__ lo) {
    __shared__ float tile[32][33];
    int b = blockIdx.z, n0 = blockIdx.x * 32, c0 = blockIdx.y * 32;
    int tx = threadIdx.x, ty = threadIdx.y;
#pragma unroll
    for (int i = 0; i < 4; i++) {
        int c = c0 + ty + i * 8;
        tile[ty + i * 8][tx] = src[((size_t)b * C_ + c) * HW_ + n0 + tx];
    }
    __syncthreads();
#pragma unroll
    for (int i = 0; i < 4; i++) {
        int n = n0 + ty + i * 8;
        int c = c0 + tx;
        float v = tile[tx][ty + i * 8];
        bf16 h = __float2bfloat16(v);
        size_t o = ((size_t)b * HW_ + n) * C_ + c;
        hi[o] = h;
        lo[o] = __float2bfloat16(v - __bfloat162float(h));
    }
}

// ---------------- launch ------------------------------------------------------
extern "C" void kernel_launch(void* const* d_in, const int* in_sizes, int n_in,
                              void* d_out, int out_size) {
    const float* x      = (const float*)d_in[0];
    const float* qkv_w  = (const float*)d_in[1];
    const float* proj_w = (const float*)d_in[2];
    const float* proj_b = (const float*)d_in[3];
    const float* temper = (const float*)d_in[4];
    const float* ln_g   = (const float*)d_in[5];
    const float* ln_b   = (const float*)d_in[6];
    const float* pos    = (const float*)d_in[7];
    const float* dw_w   = (const float*)d_in[8];
    const float* dw_b   = (const float*)d_in[9];
    const float* pw_w   = (const float*)d_in[10];
    const float* pw_b   = (const float*)d_in[11];
    float* out = (float*)d_out;

    bf16 *thi, *tlo, *w1hi, *w1lo, *w2hi, *w2lo, *w3hi, *w3lo;
    bf16 *ohi, *olo, *dThi, *dTlo, *khi, *klo, *vhi, *vlo;
    float *qkv, *rs, *ob, *y, *dw;
    cudaGetSymbolAddress((void**)&thi,  g_thi);
    cudaGetSymbolAddress((void**)&tlo,  g_tlo);
    cudaGetSymbolAddress((void**)&w1hi, g_w1hi);
    cudaGetSymbolAddress((void**)&w1lo, g_w1lo);
    cudaGetSymbolAddress((void**)&w2hi, g_w2hi);
    cudaGetSymbolAddress((void**)&w2lo, g_w2lo);
    cudaGetSymbolAddress((void**)&w3hi, g_w3hi);
    cudaGetSymbolAddress((void**)&w3lo, g_w3lo);
    cudaGetSymbolAddress((void**)&ohi,  g_ohi);
    cudaGetSymbolAddress((void**)&olo,  g_olo);
    cudaGetSymbolAddress((void**)&dThi, g_dThi);
    cudaGetSymbolAddress((void**)&dTlo, g_dTlo);
    cudaGetSymbolAddress((void**)&khi,  g_khi);
    cudaGetSymbolAddress((void**)&klo,  g_klo);
    cudaGetSymbolAddress((void**)&vhi,  g_vhi);
    cudaGetSymbolAddress((void**)&vlo,  g_vlo);
    cudaGetSymbolAddress((void**)&qkv,  g_qkv);
    cudaGetSymbolAddress((void**)&rs,   g_rs);
    cudaGetSymbolAddress((void**)&ob,   g_ob);
    cudaGetSymbolAddress((void**)&y,    g_y);
    cudaGetSymbolAddress((void**)&dw,   g_dw);

    cudaFuncSetAttribute(fat_kernel,
                         cudaFuncAttributeMaxDynamicSharedMemorySize, FAT_SMEM);
    cudaFuncSetAttribute(gemm_tc,
                         cudaFuncAttributeMaxDynamicSharedMemorySize, GSMEM);

    // weight splits
    split_kernel<<<(C3_*C_ + 255)/256, 256>>>(qkv_w, w1hi, w1lo, C3_*C_);
    split_kernel<<<(C_*C_  + 255)/256, 256>>>(proj_w, w2hi, w2lo, C_*C_);
    split_kernel<<<(C_*C_  + 255)/256, 256>>>(pw_w,  w3hi, w3lo, C_*C_);
    // t = transpose(x) + pos (bf16 split)
    build_t_kernel<<<dim3(HW_/32, C_/32, B_), dim3(32, 8)>>>(x, pos, thi, tlo);
    // qkv = t @ qkv_w^T (tensor cores)
    gemm_tc<<<dim3(C3_/128, (B_*HW_)/128, 1), 256, GSMEM>>>(
        thi, tlo, w1hi, w1lo, nullptr, nullptr, qkv, C_, C3_, 0, 0);
    // column-norm scales + K/V reshape/split
    compute_rs_kernel<<<B_*NH_, 256>>>(qkv, temper, rs);
    kvsplit_kernel<<<B_*NH_*HW_*16/256, 256>>>(qkv, khi, klo, vhi, vlo);
    // tensor-core fused attention -> o (bf16 split)
    fat_kernel<<<dim3(HW_/128, B_*NH_), 256, FAT_SMEM>>>(
        qkv, rs, khi, klo, vhi, vlo, ohi, olo);
    // proj = o @ proj_w^T + proj_b
    gemm_tc<<<dim3(C_/128, (B_*HW_)/128, 1), 256, GSMEM>>>(
        ohi, olo, w2hi, w2lo, proj_b, nullptr, ob, C_, C_, 0, 0);
    // LN + residual + transpose to [B,C,HW]
    ln_residual_kernel<<<B_*HW_, 256>>>(ob, x, ln_g, ln_b, y);
    // depthwise 3x3
    dwconv_kernel<<<dim3(B_*C_, HW_/256), 256>>>(y, dw_w, dw_b, dw);
    // transpose dw to [b][hw][c] bf16 split
    transpose_split_kernel<<<dim3(HW_/32, C_/32, B_), dim3(32, 8)>>>(dw, dThi, dTlo);
    // pointwise: out[b][c][hw] = pw_w @ dwT^T + pw_b + y
    gemm_tc<<<dim3(HW_/128, C_/128, B_), 256, GSMEM>>>(
        w3hi, w3lo, dThi, dTlo, pw_b, y, out, C_, HW_,
        (long)HW_*C_, (long)C_*HW_);
}

// round 6
// speedup vs baseline: 2.8892x; 1.0120x over previous
#include <cuda_runtime.h>
#include <cuda_bf16.h>
#include <cstdint>

#define B_  8
#define C_  512
#define H_  32
#define W_  32
#define NH_ 8
#define DH_ 64
#define HW_ 1024
#define C3_ (3*C_)

typedef __nv_bfloat16 bf16;

// ---------------- scratch (device globals; no allocation allowed) ----------
__device__ bf16  g_thi[(size_t)B_*HW_*C_];
__device__ bf16  g_tlo[(size_t)B_*HW_*C_];
__device__ bf16  g_w1hi[(size_t)C3_*C_];
__device__ bf16  g_w1lo[(size_t)C3_*C_];
__device__ bf16  g_w2hi[(size_t)C_*C_];
__device__ bf16  g_w2lo[(size_t)C_*C_];
__device__ bf16  g_w3hi[(size_t)C_*C_];
__device__ bf16  g_w3lo[(size_t)C_*C_];
__device__ float g_rs [(size_t)B_*NH_*DH_];
__device__ bf16  g_qhi[(size_t)B_*NH_*HW_*DH_];
__device__ bf16  g_qlo[(size_t)B_*NH_*HW_*DH_];
__device__ bf16  g_khi[(size_t)B_*NH_*HW_*DH_];
__device__ bf16  g_klo[(size_t)B_*NH_*HW_*DH_];
__device__ bf16  g_vhi[(size_t)B_*NH_*HW_*DH_];
__device__ bf16  g_vlo[(size_t)B_*NH_*HW_*DH_];
__device__ bf16  g_ohi[(size_t)B_*HW_*C_];
__device__ bf16  g_olo[(size_t)B_*HW_*C_];
__device__ float g_ob [(size_t)B_*HW_*C_];
__device__ float g_y  [(size_t)B_*C_*HW_];
__device__ bf16  g_dThi[(size_t)B_*HW_*C_];
__device__ bf16  g_dTlo[(size_t)B_*HW_*C_];

// ---------------- small PTX helpers -----------------------------------------
__device__ __forceinline__ uint32_t smem_u32(const void* p) {
    uint32_t a;
    asm("{ .reg .u64 t; cvta.to.shared.u64 t, %1; cvt.u32.u64 %0, t; }"
        : "=r"(a) : "l"(p));
    return a;
}
__device__ __forceinline__ void cp16(uint32_t s, const void* g) {
    asm volatile("cp.async.cg.shared.global [%0], [%1], 16;" :: "r"(s), "l"(g));
}
#define SWZ(x) ((x) ^ (((x) >> 3) & 0x70u))

__device__ __forceinline__ void ldsm4(uint32_t* r, uint32_t addr) {
    asm volatile("ldmatrix.sync.aligned.m8n8.x4.shared.b16 {%0,%1,%2,%3}, [%4];"
                 : "=r"(r[0]), "=r"(r[1]), "=r"(r[2]), "=r"(r[3]) : "r"(addr));
}
__device__ __forceinline__ void ldsm4t(uint32_t* r, uint32_t addr) {
    asm volatile("ldmatrix.sync.aligned.m8n8.x4.trans.shared.b16 {%0,%1,%2,%3}, [%4];"
                 : "=r"(r[0]), "=r"(r[1]), "=r"(r[2]), "=r"(r[3]) : "r"(addr));
}
__device__ __forceinline__ void mma16816(float* c, const uint32_t* a,
                                         const uint32_t* b) {
    asm volatile(
        "mma.sync.aligned.m16n8k16.row.col.f32.bf16.bf16.f32 "
        "{%0,%1,%2,%3}, {%4,%5,%6,%7}, {%8,%9}, {%0,%1,%2,%3};"
        : "+f"(c[0]), "+f"(c[1]), "+f"(c[2]), "+f"(c[3])
        : "r"(a[0]), "r"(a[1]), "r"(a[2]), "r"(a[3]), "r"(b[0]), "r"(b[1]));
}
__device__ __forceinline__ void split2(float a, float b, uint32_t& hi, uint32_t& lo) {
    __nv_bfloat16 ha = __float2bfloat16(a), hb = __float2bfloat16(b);
    __nv_bfloat162 h; h.x = ha; h.y = hb;
    hi = *(uint32_t*)&h;
    __nv_bfloat162 l;
    l.x = __float2bfloat16(a - __bfloat162float(ha));
    l.y = __float2bfloat16(b - __bfloat162float(hb));
    lo = *(uint32_t*)&l;
}

// ---------------- HMMA GEMM: D[128,128] = A @ B^T via bf16 hi/lo split ------
// mode 0: fp32 out (+bias,+resid). mode 1: qkv split output to g_q/k/v hi/lo.
// t3 (per CTA, from n2term): include alo*bhi term (full 3-term split).
#define GTB   16384u
#define GSMEM (1024 + 8 * 16384)

__device__ __forceinline__ void load_chunk(
    uint32_t dst, int tid, int m0, int n0, int K, int kc, bool t3,
    const bf16* __restrict__ Ahi, const bf16* __restrict__ Alo,
    const bf16* __restrict__ Bhi, const bf16* __restrict__ Blo) {
#pragma unroll
    for (int it = 0; it < 4; it++) {
        int idx = it * 256 + tid;
        int r = idx >> 3, cg = idx & 7;
        uint32_t so = SWZ((uint32_t)(r * 128 + cg * 16));
        size_t ga = (size_t)(m0 + r) * K + kc + cg * 8;
        size_t gb = (size_t)(n0 + r) * K + kc + cg * 8;
        cp16(dst            + so, Ahi + ga);
        if (t3) cp16(dst + GTB + so, Alo + ga);
        cp16(dst + 2u * GTB + so, Bhi + gb);
        cp16(dst + 3u * GTB + so, Blo + gb);
    }
    asm volatile("cp.async.commit_group;" ::: "memory");
}

__global__ __launch_bounds__(256, 1)
void gemm_tc(const bf16* __restrict__ Ahi, const bf16* __restrict__ Alo,
             const bf16* __restrict__ Bhi, const bf16* __restrict__ Blo,
             const float* __restrict__ bias, const float* __restrict__ resid,
             float* __restrict__ Cout, int K, int Nld,
             long bBatch, long cBatch, int mode, int n2term) {
    extern __shared__ char smc[];
    uint32_t sb = smem_u32(smc);
    int tid = threadIdx.x, wid = tid >> 5, lane = tid & 31;
    int m0 = blockIdx.y * 128, n0 = blockIdx.x * 128;
    const bool t3 = (n0 >= n2term);
    Bhi += (size_t)blockIdx.z * bBatch;
    Blo += (size_t)blockIdx.z * bBatch;
    if (Cout) Cout += (size_t)blockIdx.z * cBatch;
    const float* res = resid ? resid + (size_t)blockIdx.z * cBatch : nullptr;

    float* bsm = (float*)smc;
    if (tid < 128) bsm[tid] = bias ? bias[n0 + tid] : 0.f;

    const uint32_t t0 = sb + 1024;
    const int nchunk = K >> 6;
    const int mb = (wid & 3) * 32;
    const int nb = (wid >> 2) * 64;

    float acc[2][8][4];
#pragma unroll
    for (int i = 0; i < 2; i++)
#pragma unroll
        for (int j = 0; j < 8; j++)
#pragma unroll
            for (int q = 0; q < 4; q++) acc[i][j][q] = 0.f;

    load_chunk(t0, tid, m0, n0, K, 0, t3, Ahi, Alo, Bhi, Blo);
    for (int c = 0; c < nchunk; c++) {
        if (c + 1 < nchunk) {
            load_chunk(t0 + (uint32_t)((c + 1) & 1) * (4u * GTB), tid, m0, n0, K,
                       (c + 1) << 6, t3, Ahi, Alo, Bhi, Blo);
            asm volatile("cp.async.wait_group 1;" ::: "memory");
        } else {
            asm volatile("cp.async.wait_group 0;" ::: "memory");
        }
        __syncthreads();
        uint32_t bufA = t0 + (uint32_t)(c & 1) * (4u * GTB);
#pragma unroll
        for (int ks = 0; ks < 4; ks++) {
            int kb = ks * 32;
            uint32_t ao = SWZ((uint32_t)((mb + (lane & 15)) * 128 +
                                         (lane >> 4) * 16 + kb));
            uint32_t ahi[4], alo[4];
            ldsm4(ahi, bufA + ao);
            if (t3) ldsm4(alo, bufA + GTB + ao);
            uint32_t ao2 = SWZ((uint32_t)((mb + 16 + (lane & 15)) * 128 +
                                          (lane >> 4) * 16 + kb));
            uint32_t ahi2[4], alo2[4];
            ldsm4(ahi2, bufA + ao2);
            if (t3) ldsm4(alo2, bufA + GTB + ao2);
            uint32_t brow = (uint32_t)((nb + (lane & 7) + ((lane >> 4) & 1) * 8) * 128 +
                                       ((lane >> 3) & 1) * 16 + kb);
#pragma unroll
            for (int ntp = 0; ntp < 4; ntp++) {
                uint32_t bo = SWZ(brow + (uint32_t)(ntp * 16 * 128));
                uint32_t bhi[4], blo[4];
                ldsm4(bhi, bufA + 2u * GTB + bo);
                ldsm4(blo, bufA + 3u * GTB + bo);
#pragma unroll
                for (int half = 0; half < 2; half++) {
                    int nt = ntp * 2 + half;
                    const uint32_t bh[2] = {bhi[half * 2], bhi[half * 2 + 1]};
                    const uint32_t bl[2] = {blo[half * 2], blo[half * 2 + 1]};
                    mma16816(acc[0][nt], ahi, bh);
                    mma16816(acc[0][nt], ahi, bl);
                    mma16816(acc[1][nt], ahi2, bh);
                    mma16816(acc[1][nt], ahi2, bl);
                    if (t3) {
                        mma16816(acc[0][nt], alo, bh);
                        mma16816(acc[1][nt], alo2, bh);
                    }
                }
            }
        }
        __syncthreads();
    }

    int rbase = m0 + mb + (lane >> 2);
    int cbase = nb + (lane & 3) * 2;
#pragma unroll
    for (int mt = 0; mt < 2; mt++) {
#pragma unroll
        for (int nt = 0; nt < 8; nt++) {
            int ncol = cbase + nt * 8;
            int gcol = n0 + ncol;
#pragma unroll
            for (int rr = 0; rr < 2; rr++) {
                int row = rbase + mt * 16 + rr * 8;
                float v0 = acc[mt][nt][rr * 2 + 0];
                float v1 = acc[mt][nt][rr * 2 + 1];
                if (mode == 0) {
                    v0 += bsm[ncol]; v1 += bsm[ncol + 1];
                    size_t idx = (size_t)row * Nld + gcol;
                    if (res) {
                        float2 q = *(const float2*)(res + idx);
                        v0 += q.x; v1 += q.y;
                    }
                    float2 o; o.x = v0; o.y = v1;
                    *(float2*)(Cout + idx) = o;
                } else {
                    // qkv split output: [bh][token][64] head-major hi/lo
                    int b = row >> 10, tok = row & 1023;
                    int region = gcol >> 9;        // 0=q 1=k 2=v
                    int hd = gcol & 511;
                    int h = hd >> 6, d = hd & 63;
                    size_t dst = (((size_t)(b * NH_ + h) * HW_) + tok) * DH_ + d;
                    uint32_t hi, lo;
                    split2(v0, v1, hi, lo);
                    bf16* ph = (region == 0) ? g_qhi : (region == 1) ? g_khi : g_vhi;
                    bf16* pl = (region == 0) ? g_qlo : (region == 1) ? g_klo : g_vlo;
                    *(uint32_t*)&ph[dst] = hi;
                    *(uint32_t*)&pl[dst] = lo;
                }
            }
        }
    }
}

// ---------------- 1) t = transpose(x) + pos -> bf16 hi/lo --------------------
__global__ void build_t_kernel(const float* __restrict__ x,
                               const float* __restrict__ pos,
                               bf16* __restrict__ thi, bf16* __restrict__ tlo) {
    __shared__ float tile[32][33];
    int b  = blockIdx.z;
    int n0 = blockIdx.x * 32;
    int c0 = blockIdx.y * 32;
    int tx = threadIdx.x, ty = threadIdx.y;
#pragma unroll
    for (int i = 0; i < 4; i++) {
        int c = c0 + ty + i * 8;
        tile[ty + i * 8][tx] = x[((size_t)b * C_ + c) * HW_ + n0 + tx];
    }
    __syncthreads();
#pragma unroll
    for (int i = 0; i < 4; i++) {
        int n = n0 + ty + i * 8;
        int c = c0 + tx;
        float v = tile[tx][ty + i * 8] + pos[(size_t)n * C_ + c];
        bf16 h = __float2bfloat16(v);
        size_t o = ((size_t)b * HW_ + n) * C_ + c;
        thi[o] = h;
        tlo[o] = __float2bfloat16(v - __bfloat162float(h));
    }
}

// ---------------- fused weight splits ----------------------------------------
#define NW1 (C3_*C_)
#define NW2 (C_*C_)
__global__ void splitw_kernel(const float* __restrict__ w1,
                              const float* __restrict__ w2,
                              const float* __restrict__ w3) {
    int i = blockIdx.x * 256 + threadIdx.x;
    const float* src; bf16 *hi, *lo; int idx;
    if (i < NW1)            { src = w1; hi = g_w1hi; lo = g_w1lo; idx = i; }
    else if (i < NW1 + NW2) { src = w2; hi = g_w2hi; lo = g_w2lo; idx = i - NW1; }
    else if (i < NW1+2*NW2) { src = w3; hi = g_w3hi; lo = g_w3lo; idx = i - NW1 - NW2; }
    else return;
    float v = src[idx];
    bf16 h = __float2bfloat16(v);
    hi[idx] = h;
    lo[idx] = __float2bfloat16(v - __bfloat162float(h));
}

// ---------------- per-(b,h,d) column norms of q,k -> rs ----------------------
__global__ void compute_rs_kernel(const float* __restrict__ temp,
                                  float* __restrict__ rs) {
    int bh = blockIdx.x;
    int h = bh % NH_;
    int d = threadIdx.x & 63;
    int part = threadIdx.x >> 6;
    float sq = 0.f, sk = 0.f;
    size_t base = (size_t)bh * HW_ * DH_ + d;
    for (int n = part; n < HW_; n += 4) {
        size_t off = base + (size_t)n * DH_;
        float qv = __bfloat162float(g_qhi[off]) + __bfloat162float(g_qlo[off]);
        float kv = __bfloat162float(g_khi[off]) + __bfloat162float(g_klo[off]);
        sq += qv * qv;
        sk += kv * kv;
    }
    __shared__ float smq[4][64], smk[4][64];
    smq[part][d] = sq; smk[part][d] = sk;
    __syncthreads();
    if (threadIdx.x < 64) {
        float q = smq[0][d] + smq[1][d] + smq[2][d] + smq[3][d];
        float k = smk[0][d] + smk[1][d] + smk[2][d] + smk[3][d];
        float qn = fmaxf(sqrtf(q), 1e-12f);
        float kn = fmaxf(sqrtf(k), 1e-12f);
        rs[(size_t)bh * DH_ + d] = temp[h] / (qn * kn);
    }
}

// ---------------- tensor-core fused flash attention --------------------------
// S = qh*kh + ql*kh (2-term: logits tiny -> absolute err ~1e-4). O 3-term.
#define FAT_STAGE 24576u
#define FAT_SMEM  (2 * 24576 + 256)

__device__ __forceinline__ void fat_loadkv(
    uint32_t buf, int tid, size_t kvbase, int kc,
    const bf16* __restrict__ khi,
    const bf16* __restrict__ vhi, const bf16* __restrict__ vlo) {
#pragma unroll
    for (int it = 0; it < 2; it++) {
        int idx = it * 256 + tid;
        int r = idx >> 3, cg = idx & 7;
        uint32_t so = SWZ((uint32_t)(r * 128 + cg * 16));
        size_t g = kvbase + (size_t)(kc + r) * DH_ + cg * 8;
        cp16(buf +     0u + so, khi + g);
        cp16(buf +  8192u + so, vhi + g);
        cp16(buf + 16384u + so, vlo + g);
    }
    asm volatile("cp.async.commit_group;" ::: "memory");
}

__global__ __launch_bounds__(256, 1)
void fat_kernel(const bf16* __restrict__ qhi, const bf16* __restrict__ qlo,
                const float* __restrict__ rs,
                const bf16* __restrict__ khi,
                const bf16* __restrict__ vhi, const bf16* __restrict__ vlo,
                bf16* __restrict__ ohi, bf16* __restrict__ olo) {
    extern __shared__ char smc[];
    uint32_t sb = smem_u32(smc);
    float* rss = (float*)(smc + 2 * FAT_STAGE);
    int bh = blockIdx.y;
    int b = bh >> 3, h = bh & 7;
    int q0 = blockIdx.x * 128;
    int tid = threadIdx.x, wid = tid >> 5, lane = tid & 31;
    int mb = wid * 16;

    if (tid < 64) rss[tid] = rs[bh * DH_ + tid];
    __syncthreads();

    // stage Q (hi+lo, scaled by rs) hi/lo into smem
#pragma unroll
    for (int v = 0; v < 8; v++) {
        int idx = v * 256 + tid;
        int row = idx >> 4, dq = (idx & 15) * 4;
        size_t qoff = ((size_t)bh * HW_ + q0 + row) * DH_ + dq;
        __nv_bfloat162 ha = *(const __nv_bfloat162*)&qhi[qoff];
        __nv_bfloat162 hb = *(const __nv_bfloat162*)&qhi[qoff + 2];
        __nv_bfloat162 la = *(const __nv_bfloat162*)&qlo[qoff];
        __nv_bfloat162 lb = *(const __nv_bfloat162*)&qlo[qoff + 2];
        float qx = (__bfloat162float(ha.x) + __bfloat162float(la.x)) * rss[dq];
        float qy = (__bfloat162float(ha.y) + __bfloat162float(la.y)) * rss[dq + 1];
        float qz = (__bfloat162float(hb.x) + __bfloat162float(lb.x)) * rss[dq + 2];
        float qw = (__bfloat162float(hb.y) + __bfloat162float(lb.y)) * rss[dq + 3];
        uint32_t h0, l0, h1, l1;
        split2(qx, qy, h0, l0);
        split2(qz, qw, h1, l1);
        uint32_t off = SWZ((uint32_t)(row * 128 + dq * 2));
        *(uint32_t*)(smc + off)             = h0;
        *(uint32_t*)(smc + off + 4)         = h1;
        *(uint32_t*)(smc + 16384 + off)     = l0;
        *(uint32_t*)(smc + 16384 + off + 4) = l1;
    }
    __syncthreads();

    // Q fragments to registers
    uint32_t qh[4][4], ql[4][4];
#pragma unroll
    for (int ks = 0; ks < 4; ks++) {
        uint32_t ao = SWZ((uint32_t)((mb + (lane & 15)) * 128 +
                                     (lane >> 4) * 16 + ks * 32));
        ldsm4(qh[ks], sb + ao);
        ldsm4(ql[ks], sb + 16384 + ao);
    }
    __syncthreads();

    float o[8][4];
#pragma unroll
    for (int j = 0; j < 8; j++)
#pragma unroll
        for (int q = 0; q < 4; q++) o[j][q] = 0.f;
    float m0 = -1e30f, m1 = -1e30f, l0 = 0.f, l1 = 0.f;
    const size_t kvbase = (size_t)bh * HW_ * DH_;

    fat_loadkv(sb, tid, kvbase, 0, khi, vhi, vlo);
    for (int kt = 0; kt < 16; kt++) {
        uint32_t cur = sb + (uint32_t)(kt & 1) * FAT_STAGE;
        if (kt + 1 < 16) {
            fat_loadkv(sb + (uint32_t)((kt + 1) & 1) * FAT_STAGE, tid, kvbase,
                       (kt + 1) * 64, khi, vhi, vlo);
            asm volatile("cp.async.wait_group 1;" ::: "memory");
        } else {
            asm volatile("cp.async.wait_group 0;" ::: "memory");
        }
        __syncthreads();

        // ---- S = Q.K^T (2-term)
        float s[8][4];
#pragma unroll
        for (int j = 0; j < 8; j++)
#pragma unroll
            for (int q = 0; q < 4; q++) s[j][q] = 0.f;
#pragma unroll
        for (int ks = 0; ks < 4; ks++) {
            uint32_t brow = (uint32_t)(((lane & 7) + ((lane >> 4) & 1) * 8) * 128 +
                                       ((lane >> 3) & 1) * 16 + ks * 32);
#pragma unroll
            for (int np = 0; np < 4; np++) {
                uint32_t bo = SWZ(brow + (uint32_t)(np * 16 * 128));
                uint32_t kh4[4];
                ldsm4(kh4, cur + bo);
#pragma unroll
                for (int half = 0; half < 2; half++) {
                    int j = np * 2 + half;
                    const uint32_t bhh[2] = {kh4[half * 2], kh4[half * 2 + 1]};
                    mma16816(s[j], qh[ks], bhh);
                    mma16816(s[j], ql[ks], bhh);
                }
            }
        }

        // ---- online softmax (rows r=lane>>2 and r+8; quads share rows)
        float mx0 = -1e30f, mx1 = -1e30f;
#pragma unroll
        for (int j = 0; j < 8; j++) {
            mx0 = fmaxf(mx0, fmaxf(s[j][0], s[j][1]));
            mx1 = fmaxf(mx1, fmaxf(s[j][2], s[j][3]));
        }
        mx0 = fmaxf(mx0, __shfl_xor_sync(0xffffffffu, mx0, 1));
        mx0 = fmaxf(mx0, __shfl_xor_sync(0xffffffffu, mx0, 2));
        mx1 = fmaxf(mx1, __shfl_xor_sync(0xffffffffu, mx1, 1));
        mx1 = fmaxf(mx1, __shfl_xor_sync(0xffffffffu, mx1, 2));
        float mn0 = fmaxf(m0, mx0), mn1 = fmaxf(m1, mx1);
        float al0 = __expf(m0 - mn0), al1 = __expf(m1 - mn1);
        float sum0 = 0.f, sum1 = 0.f;
#pragma unroll
        for (int j = 0; j < 8; j++) {
            s[j][0] = __expf(s[j][0] - mn0);
            s[j][1] = __expf(s[j][1] - mn0);
            s[j][2] = __expf(s[j][2] - mn1);
            s[j][3] = __expf(s[j][3] - mn1);
            sum0 += s[j][0] + s[j][1];
            sum1 += s[j][2] + s[j][3];
        }
        sum0 += __shfl_xor_sync(0xffffffffu, sum0, 1);
        sum0 += __shfl_xor_sync(0xffffffffu, sum0, 2);
        sum1 += __shfl_xor_sync(0xffffffffu, sum1, 1);
        sum1 += __shfl_xor_sync(0xffffffffu, sum1, 2);
        l0 = l0 * al0 + sum0; l1 = l1 * al1 + sum1;
        m0 = mn0; m1 = mn1;
#pragma unroll
        for (int j = 0; j < 8; j++) {
            o[j][0] *= al0; o[j][1] *= al0;
            o[j][2] *= al1; o[j][3] *= al1;
        }

        // ---- O += P.V (3-term); P frags packed straight from S frags
#pragma unroll
        for (int ks = 0; ks < 4; ks++) {
            int j0 = 2 * ks, j1 = 2 * ks + 1;
            uint32_t ph[4], pl[4];
            split2(s[j0][0], s[j0][1], ph[0], pl[0]);
            split2(s[j0][2], s[j0][3], ph[1], pl[1]);
            split2(s[j1][0], s[j1][1], ph[2], pl[2]);
            split2(s[j1][2], s[j1][3], ph[3], pl[3]);
            uint32_t vrow = (uint32_t)((ks * 16 + (lane & 7) + ((lane >> 3) & 1) * 8) * 128 +
                                       ((lane >> 4) & 1) * 16);
#pragma unroll
            for (int np = 0; np < 4; np++) {
                uint32_t vo = SWZ(vrow + (uint32_t)(np * 32));
                uint32_t vh4[4], vl4[4];
                ldsm4t(vh4, cur +  8192u + vo);
                ldsm4t(vl4, cur + 16384u + vo);
#pragma unroll
                for (int half = 0; half < 2; half++) {
                    int j = np * 2 + half;
                    const uint32_t bvh[2] = {vh4[half * 2], vh4[half * 2 + 1]};
                    const uint32_t bvl[2] = {vl4[half * 2], vl4[half * 2 + 1]};
                    mma16816(o[j], ph, bvh);
                    mma16816(o[j], ph, bvl);
                    mma16816(o[j], pl, bvh);
                }
            }
        }
        __syncthreads();
    }

    // epilogue: normalize, split, store
    float inv0 = 1.f / l0, inv1 = 1.f / l1;
    int r0 = lane >> 2, cc = (lane & 3) * 2;
    int row0 = q0 + mb + r0, row1 = row0 + 8;
#pragma unroll
    for (int j = 0; j < 8; j++) {
        int col = h * DH_ + j * 8 + cc;
        size_t off0 = ((size_t)(b * HW_ + row0)) * C_ + col;
        size_t off1 = ((size_t)(b * HW_ + row1)) * C_ + col;
        uint32_t hi, lo;
        split2(o[j][0] * inv0, o[j][1] * inv0, hi, lo);
        *(uint32_t*)&ohi[off0] = hi; *(uint32_t*)&olo[off0] = lo;
        split2(o[j][2] * inv1, o[j][3] * inv1, hi, lo);
        *(uint32_t*)&ohi[off1] = hi; *(uint32_t*)&olo[off1] = lo;
    }
}

// ---------------- LayerNorm over C + residual + transpose to [B,C,HW] -------
__global__ void ln_residual_kernel(const float* __restrict__ ob,
                                   const float* __restrict__ x,
                                   const float* __restrict__ g,
                                   const float* __restrict__ be,
                                   float* __restrict__ y) {
    int row = blockIdx.x;
    int b = row >> 10, n = row & 1023;
    const float* pr = ob + (size_t)row * C_;
    int tid = threadIdx.x;
    float v0 = pr[tid], v1 = pr[tid + 256];
    __shared__ float red[256];
    red[tid] = v0 + v1; __syncthreads();
    for (int s = 128; s > 0; s >>= 1) {
        if (tid < s) red[tid] += red[tid + s];
        __syncthreads();
    }
    float mean = red[0] * (1.0f / C_);
    __syncthreads();
    float d0 = v0 - mean, d1 = v1 - mean;
    red[tid] = d0 * d0 + d1 * d1; __syncthreads();
    for (int s = 128; s > 0; s >>= 1) {
        if (tid < s) red[tid] += red[tid + s];
        __syncthreads();
    }
    float rstd = rsqrtf(red[0] * (1.0f / C_) + 1e-5f);
    int c0 = tid, c1 = tid + 256;
    size_t i0 = ((size_t)b * C_ + c0) * HW_ + n;
    size_t i1 = ((size_t)b * C_ + c1) * HW_ + n;
    y[i0] = d0 * rstd * g[c0] + be[c0] + x[i0];
    y[i1] = d1 * rstd * g[c1] + be[c1] + x[i1];
}

// ---------------- fused depthwise 3x3 + transpose + split --------------------
// block: (h row, 32-channel tile, b). Computes dw conv and writes [b][hw][c]
// hi/lo bf16 directly.
__global__ void dwt_kernel(const float* __restrict__ y,
                           const float* __restrict__ w,
                           const float* __restrict__ bias,
                           bf16* __restrict__ hi, bf16* __restrict__ lo) {
    __shared__ float yt[32][3][33];
    __shared__ float ot[32][33];   // [w][c]
    int hh = blockIdx.x, c0 = blockIdx.y * 32, b = blockIdx.z;
    int tid = threadIdx.x;
    int c = tid >> 3, wg = (tid & 7) * 4;

#pragma unroll
    for (int r = 0; r < 3; r++) {
        int ih = hh + r - 1;
        float4 v = make_float4(0.f, 0.f, 0.f, 0.f);
        if (ih >= 0 && ih < H_)
            v = *(const float4*)&y[((size_t)(b * C_ + c0 + c)) * HW_ + ih * W_ + wg];
        yt[c][r][wg + 0] = v.x; yt[c][r][wg + 1] = v.y;
        yt[c][r][wg + 2] = v.z; yt[c][r][wg + 3] = v.w;
    }
    float wc[9];
#pragma unroll
    for (int i = 0; i < 9; i++) wc[i] = w[(c0 + c) * 9 + i];
    float bs = bias[c0 + c];
    __syncthreads();

#pragma unroll
    for (int j = 0; j < 4; j++) {
        int ww = wg + j;
        float acc = bs;
#pragma unroll
        for (int ki = 0; ki < 3; ki++)
#pragma unroll
            for (int kj = 0; kj < 3; kj++) {
                int iw = ww + kj - 1;
                if (iw >= 0 && iw < W_) acc += wc[ki * 3 + kj] * yt[c][ki][iw];
            }
        ot[ww][c] = acc;
    }
    __syncthreads();

    int w2 = tid >> 3, cg = (tid & 7) * 4;
    int token = hh * W_ + w2;
    size_t base = ((size_t)b * HW_ + token) * C_ + c0 + cg;
    float a0 = ot[w2][cg], a1 = ot[w2][cg + 1];
    float a2 = ot[w2][cg + 2], a3 = ot[w2][cg + 3];
    uint32_t h0, l0, h1, l1;
    split2(a0, a1, h0, l0);
    split2(a2, a3, h1, l1);
    *(uint32_t*)&hi[base]     = h0; *(uint32_t*)&hi[base + 2] = h1;
    *(uint32_t*)&lo[base]     = l0; *(uint32_t*)&lo[base + 2] = l1;
}

// ---------------- launch ------------------------------------------------------
extern "C" void kernel_launch(void* const* d_in, const int* in_sizes, int n_in,
                              void* d_out, int out_size) {
    const float* x      = (const float*)d_in[0];
    const float* qkv_w  = (const float*)d_in[1];
    const float* proj_w = (const float*)d_in[2];
    const float* proj_b = (const float*)d_in[3];
    const float* temper = (const float*)d_in[4];
    const float* ln_g   = (const float*)d_in[5];
    const float* ln_b   = (const float*)d_in[6];
    const float* pos    = (const float*)d_in[7];
    const float* dw_w   = (const float*)d_in[8];
    const float* dw_b   = (const float*)d_in[9];
    const float* pw_w   = (const float*)d_in[10];
    const float* pw_b   = (const float*)d_in[11];
    float* out = (float*)d_out;

    bf16 *thi, *tlo, *w1hi, *w1lo, *w2hi, *w2lo, *w3hi, *w3lo;
    bf16 *ohi, *olo, *dThi, *dTlo, *qhi, *qlo, *khi, *vhi, *vlo;
    float *rs, *ob, *y;
    cudaGetSymbolAddress((void**)&thi,  g_thi);
    cudaGetSymbolAddress((void**)&tlo,  g_tlo);
    cudaGetSymbolAddress((void**)&w1hi, g_w1hi);
    cudaGetSymbolAddress((void**)&w1lo, g_w1lo);
    cudaGetSymbolAddress((void**)&w2hi, g_w2hi);
    cudaGetSymbolAddress((void**)&w2lo, g_w2lo);
    cudaGetSymbolAddress((void**)&w3hi, g_w3hi);
    cudaGetSymbolAddress((void**)&w3lo, g_w3lo);
    cudaGetSymbolAddress((void**)&ohi,  g_ohi);
    cudaGetSymbolAddress((void**)&olo,  g_olo);
    cudaGetSymbolAddress((void**)&dThi, g_dThi);
    cudaGetSymbolAddress((void**)&dTlo, g_dTlo);
    cudaGetSymbolAddress((void**)&qhi,  g_qhi);
    cudaGetSymbolAddress((void**)&qlo,  g_qlo);
    cudaGetSymbolAddress((void**)&khi,  g_khi);
    cudaGetSymbolAddress((void**)&vhi,  g_vhi);
    cudaGetSymbolAddress((void**)&vlo,  g_vlo);
    cudaGetSymbolAddress((void**)&rs,   g_rs);
    cudaGetSymbolAddress((void**)&ob,   g_ob);
    cudaGetSymbolAddress((void**)&y,    g_y);

    cudaFuncSetAttribute(fat_kernel,
                         cudaFuncAttributeMaxDynamicSharedMemorySize, FAT_SMEM);
    cudaFuncSetAttribute(gemm_tc,
                         cudaFuncAttributeMaxDynamicSharedMemorySize, GSMEM);

    // fused weight splits
    splitw_kernel<<<(NW1 + 2*NW2 + 255)/256, 256>>>(qkv_w, proj_w, pw_w);
    // t = transpose(x) + pos (bf16 split)
    build_t_kernel<<<dim3(HW_/32, C_/32, B_), dim3(32, 8)>>>(x, pos, thi, tlo);
    // qkv GEMM: q,k columns 2-term; v columns 3-term; split head-major output
    gemm_tc<<<dim3(C3_/128, (B_*HW_)/128, 1), 256, GSMEM>>>(
        thi, tlo, w1hi, w1lo, nullptr, nullptr, nullptr, C_, 0, 0, 0,
        1 /*mode=qkv*/, 1024 /*n2term: v cols 3-term*/);
    // column-norm scales
    compute_rs_kernel<<<B_*NH_, 256>>>(temper, rs);
    // tensor-core fused attention -> o (bf16 split)
    fat_kernel<<<dim3(HW_/128, B_*NH_), 256, FAT_SMEM>>>(
        qhi, qlo, rs, khi, vhi, vlo, ohi, olo);
    // proj = o @ proj_w^T + proj_b (full 3-term)
    gemm_tc<<<dim3(C_/128, (B_*HW_)/128, 1), 256, GSMEM>>>(
        ohi, olo, w2hi, w2lo, proj_b, nullptr, ob, C_, C_, 0, 0, 0, 0);
    // LN + residual + transpose to [B,C,HW]
    ln_residual_kernel<<<B_*HW_, 256>>>(ob, x, ln_g, ln_b, y);
    // fused depthwise 3x3 + transpose + split
    dwt_kernel<<<dim3(H_, C_/32, B_), 256>>>(y, dw_w, dw_b, dThi, dTlo);
    // pointwise (2-term: conv term is ~3% of output) + bias + residual -> out
    gemm_tc<<<dim3(HW_/128, C_/128, B_), 256, GSMEM>>>(
        w3hi, w3lo, dThi, dTlo, pw_b, y, out, C_, HW_,
        (long)HW_*C_, (long)C_*HW_, 0, 1 << 30);
}

// round 7
// speedup vs baseline: 3.2439x; 1.1228x over previous
#include <cuda_runtime.h>
#include <cuda_bf16.h>
#include <cstdint>

#define B_  8
#define C_  512
#define H_  32
#define W_  32
#define NH_ 8
#define DH_ 64
#define HW_ 1024
#define C3_ (3*C_)

typedef __nv_bfloat16 bf16;

// ---------------- scratch (device globals; no allocation allowed) ----------
__device__ bf16  g_thi[(size_t)B_*HW_*C_];
__device__ bf16  g_tlo[(size_t)B_*HW_*C_];
__device__ bf16  g_w1hi[(size_t)C3_*C_];
__device__ bf16  g_w1lo[(size_t)C3_*C_];
__device__ bf16  g_w2hi[(size_t)C_*C_];
__device__ bf16  g_w2lo[(size_t)C_*C_];
__device__ bf16  g_w3hi[(size_t)C_*C_];
__device__ bf16  g_w3lo[(size_t)C_*C_];
__device__ float g_rs [(size_t)B_*NH_*DH_];
__device__ float g_psq[(size_t)B_*NH_*16*DH_];
__device__ float g_psk[(size_t)B_*NH_*16*DH_];
__device__ bf16  g_qhi[(size_t)B_*NH_*HW_*DH_];
__device__ bf16  g_qlo[(size_t)B_*NH_*HW_*DH_];
__device__ bf16  g_khi[(size_t)B_*NH_*HW_*DH_];
__device__ bf16  g_klo[(size_t)B_*NH_*HW_*DH_];
__device__ bf16  g_vhi[(size_t)B_*NH_*HW_*DH_];
__device__ bf16  g_vlo[(size_t)B_*NH_*HW_*DH_];
__device__ bf16  g_ohi[(size_t)B_*HW_*C_];
__device__ bf16  g_olo[(size_t)B_*HW_*C_];
__device__ float g_ob [(size_t)B_*HW_*C_];
__device__ float g_y  [(size_t)B_*C_*HW_];
__device__ bf16  g_dThi[(size_t)B_*HW_*C_];
__device__ bf16  g_dTlo[(size_t)B_*HW_*C_];

// ---------------- small PTX helpers -----------------------------------------
__device__ __forceinline__ uint32_t smem_u32(const void* p) {
    uint32_t a;
    asm("{ .reg .u64 t; cvta.to.shared.u64 t, %1; cvt.u32.u64 %0, t; }"
        : "=r"(a) : "l"(p));
    return a;
}
__device__ __forceinline__ void cp16(uint32_t s, const void* g) {
    asm volatile("cp.async.cg.shared.global [%0], [%1], 16;" :: "r"(s), "l"(g));
}
#define SWZ(x) ((x) ^ (((x) >> 3) & 0x70u))

__device__ __forceinline__ void ldsm4(uint32_t* r, uint32_t addr) {
    asm volatile("ldmatrix.sync.aligned.m8n8.x4.shared.b16 {%0,%1,%2,%3}, [%4];"
                 : "=r"(r[0]), "=r"(r[1]), "=r"(r[2]), "=r"(r[3]) : "r"(addr));
}
__device__ __forceinline__ void ldsm4t(uint32_t* r, uint32_t addr) {
    asm volatile("ldmatrix.sync.aligned.m8n8.x4.trans.shared.b16 {%0,%1,%2,%3}, [%4];"
                 : "=r"(r[0]), "=r"(r[1]), "=r"(r[2]), "=r"(r[3]) : "r"(addr));
}
__device__ __forceinline__ void mma16816(float* c, const uint32_t* a,
                                         const uint32_t* b) {
    asm volatile(
        "mma.sync.aligned.m16n8k16.row.col.f32.bf16.bf16.f32 "
        "{%0,%1,%2,%3}, {%4,%5,%6,%7}, {%8,%9}, {%0,%1,%2,%3};"
        : "+f"(c[0]), "+f"(c[1]), "+f"(c[2]), "+f"(c[3])
        : "r"(a[0]), "r"(a[1]), "r"(a[2]), "r"(a[3]), "r"(b[0]), "r"(b[1]));
}
__device__ __forceinline__ void split2(float a, float b, uint32_t& hi, uint32_t& lo) {
    __nv_bfloat16 ha = __float2bfloat16(a), hb = __float2bfloat16(b);
    __nv_bfloat162 h; h.x = ha; h.y = hb;
    hi = *(uint32_t*)&h;
    __nv_bfloat162 l;
    l.x = __float2bfloat16(a - __bfloat162float(ha));
    l.y = __float2bfloat16(b - __bfloat162float(hb));
    lo = *(uint32_t*)&l;
}

// ---------------- HMMA GEMM: D[128,128] = A @ B^T via bf16 hi/lo split ------
#define GTB   16384u
#define GSMEM (1024 + 8 * 16384)

__device__ __forceinline__ void load_chunk(
    uint32_t dst, int tid, int m0, int n0, int K, int kc, bool t3,
    const bf16* __restrict__ Ahi, const bf16* __restrict__ Alo,
    const bf16* __restrict__ Bhi, const bf16* __restrict__ Blo) {
#pragma unroll
    for (int it = 0; it < 4; it++) {
        int idx = it * 256 + tid;
        int r = idx >> 3, cg = idx & 7;
        uint32_t so = SWZ((uint32_t)(r * 128 + cg * 16));
        size_t ga = (size_t)(m0 + r) * K + kc + cg * 8;
        size_t gb = (size_t)(n0 + r) * K + kc + cg * 8;
        cp16(dst            + so, Ahi + ga);
        if (t3) cp16(dst + GTB + so, Alo + ga);
        cp16(dst + 2u * GTB + so, Bhi + gb);
        cp16(dst + 3u * GTB + so, Blo + gb);
    }
    asm volatile("cp.async.commit_group;" ::: "memory");
}

__global__ __launch_bounds__(256, 1)
void gemm_tc(const bf16* __restrict__ Ahi, const bf16* __restrict__ Alo,
             const bf16* __restrict__ Bhi, const bf16* __restrict__ Blo,
             const float* __restrict__ bias, const float* __restrict__ resid,
             float* __restrict__ Cout, int K, int Nld,
             long bBatch, long cBatch, int mode, int n2term) {
    extern __shared__ char smc[];
    uint32_t sb = smem_u32(smc);
    int tid = threadIdx.x, wid = tid >> 5, lane = tid & 31;
    int m0 = blockIdx.y * 128, n0 = blockIdx.x * 128;
    const bool t3 = (n0 >= n2term);
    Bhi += (size_t)blockIdx.z * bBatch;
    Blo += (size_t)blockIdx.z * bBatch;
    if (Cout) Cout += (size_t)blockIdx.z * cBatch;
    const float* res = resid ? resid + (size_t)blockIdx.z * cBatch : nullptr;

    float* bsm = (float*)smc;
    if (tid < 128) bsm[tid] = bias ? bias[n0 + tid] : 0.f;

    const uint32_t t0 = sb + 1024;
    const int nchunk = K >> 6;
    const int mb = (wid & 3) * 32;
    const int nb = (wid >> 2) * 64;

    float acc[2][8][4];
#pragma unroll
    for (int i = 0; i < 2; i++)
#pragma unroll
        for (int j = 0; j < 8; j++)
#pragma unroll
            for (int q = 0; q < 4; q++) acc[i][j][q] = 0.f;

    load_chunk(t0, tid, m0, n0, K, 0, t3, Ahi, Alo, Bhi, Blo);
    for (int c = 0; c < nchunk; c++) {
        if (c + 1 < nchunk) {
            load_chunk(t0 + (uint32_t)((c + 1) & 1) * (4u * GTB), tid, m0, n0, K,
                       (c + 1) << 6, t3, Ahi, Alo, Bhi, Blo);
            asm volatile("cp.async.wait_group 1;" ::: "memory");
        } else {
            asm volatile("cp.async.wait_group 0;" ::: "memory");
        }
        __syncthreads();
        uint32_t bufA = t0 + (uint32_t)(c & 1) * (4u * GTB);
#pragma unroll
        for (int ks = 0; ks < 4; ks++) {
            int kb = ks * 32;
            uint32_t ao = SWZ((uint32_t)((mb + (lane & 15)) * 128 +
                                         (lane >> 4) * 16 + kb));
            uint32_t ahi[4], alo[4];
            ldsm4(ahi, bufA + ao);
            if (t3) ldsm4(alo, bufA + GTB + ao);
            uint32_t ao2 = SWZ((uint32_t)((mb + 16 + (lane & 15)) * 128 +
                                          (lane >> 4) * 16 + kb));
            uint32_t ahi2[4], alo2[4];
            ldsm4(ahi2, bufA + ao2);
            if (t3) ldsm4(alo2, bufA + GTB + ao2);
            uint32_t brow = (uint32_t)((nb + (lane & 7) + ((lane >> 4) & 1) * 8) * 128 +
                                       ((lane >> 3) & 1) * 16 + kb);
#pragma unroll
            for (int ntp = 0; ntp < 4; ntp++) {
                uint32_t bo = SWZ(brow + (uint32_t)(ntp * 16 * 128));
                uint32_t bhi[4], blo[4];
                ldsm4(bhi, bufA + 2u * GTB + bo);
                ldsm4(blo, bufA + 3u * GTB + bo);
#pragma unroll
                for (int half = 0; half < 2; half++) {
                    int nt = ntp * 2 + half;
                    const uint32_t bh[2] = {bhi[half * 2], bhi[half * 2 + 1]};
                    const uint32_t bl[2] = {blo[half * 2], blo[half * 2 + 1]};
                    mma16816(acc[0][nt], ahi, bh);
                    mma16816(acc[0][nt], ahi, bl);
                    mma16816(acc[1][nt], ahi2, bh);
                    mma16816(acc[1][nt], ahi2, bl);
                    if (t3) {
                        mma16816(acc[0][nt], alo, bh);
                        mma16816(acc[1][nt], alo2, bh);
                    }
                }
            }
        }
        __syncthreads();
    }

    int rbase = m0 + mb + (lane >> 2);
    int cbase = nb + (lane & 3) * 2;
#pragma unroll
    for (int mt = 0; mt < 2; mt++) {
#pragma unroll
        for (int nt = 0; nt < 8; nt++) {
            int ncol = cbase + nt * 8;
            int gcol = n0 + ncol;
#pragma unroll
            for (int rr = 0; rr < 2; rr++) {
                int row = rbase + mt * 16 + rr * 8;
                float v0 = acc[mt][nt][rr * 2 + 0];
                float v1 = acc[mt][nt][rr * 2 + 1];
                if (mode == 0) {
                    v0 += bsm[ncol]; v1 += bsm[ncol + 1];
                    size_t idx = (size_t)row * Nld + gcol;
                    if (res) {
                        float2 q = *(const float2*)(res + idx);
                        v0 += q.x; v1 += q.y;
                    }
                    float2 o; o.x = v0; o.y = v1;
                    *(float2*)(Cout + idx) = o;
                } else {
                    int b = row >> 10, tok = row & 1023;
                    int region = gcol >> 9;        // 0=q 1=k 2=v
                    int hd = gcol & 511;
                    int h = hd >> 6, d = hd & 63;
                    size_t dst = (((size_t)(b * NH_ + h) * HW_) + tok) * DH_ + d;
                    uint32_t hi, lo;
                    split2(v0, v1, hi, lo);
                    bf16* ph = (region == 0) ? g_qhi : (region == 1) ? g_khi : g_vhi;
                    bf16* pl = (region == 0) ? g_qlo : (region == 1) ? g_klo : g_vlo;
                    *(uint32_t*)&ph[dst] = hi;
                    *(uint32_t*)&pl[dst] = lo;
                }
            }
        }
    }
}

// ---------------- 1) t = transpose(x) + pos -> bf16 hi/lo --------------------
__global__ void build_t_kernel(const float* __restrict__ x,
                               const float* __restrict__ pos,
                               bf16* __restrict__ thi, bf16* __restrict__ tlo) {
    __shared__ float tile[32][33];
    int b  = blockIdx.z;
    int n0 = blockIdx.x * 32;
    int c0 = blockIdx.y * 32;
    int tx = threadIdx.x, ty = threadIdx.y;
#pragma unroll
    for (int i = 0; i < 4; i++) {
        int c = c0 + ty + i * 8;
        tile[ty + i * 8][tx] = x[((size_t)b * C_ + c) * HW_ + n0 + tx];
    }
    __syncthreads();
#pragma unroll
    for (int i = 0; i < 4; i++) {
        int n = n0 + ty + i * 8;
        int c = c0 + tx;
        float v = tile[tx][ty + i * 8] + pos[(size_t)n * C_ + c];
        bf16 h = __float2bfloat16(v);
        size_t o = ((size_t)b * HW_ + n) * C_ + c;
        thi[o] = h;
        tlo[o] = __float2bfloat16(v - __bfloat162float(h));
    }
}

// ---------------- fused weight splits ----------------------------------------
#define NW1 (C3_*C_)
#define NW2 (C_*C_)
__global__ void splitw_kernel(const float* __restrict__ w1,
                              const float* __restrict__ w2,
                              const float* __restrict__ w3) {
    int i = blockIdx.x * 256 + threadIdx.x;
    const float* src; bf16 *hi, *lo; int idx;
    if (i < NW1)            { src = w1; hi = g_w1hi; lo = g_w1lo; idx = i; }
    else if (i < NW1 + NW2) { src = w2; hi = g_w2hi; lo = g_w2lo; idx = i - NW1; }
    else if (i < NW1+2*NW2) { src = w3; hi = g_w3hi; lo = g_w3lo; idx = i - NW1 - NW2; }
    else return;
    float v = src[idx];
    bf16 h = __float2bfloat16(v);
    hi[idx] = h;
    lo[idx] = __float2bfloat16(v - __bfloat162float(h));
}

// ---------------- rs two-stage reduction -------------------------------------
// stage1: grid 1024 = (bh, 16 token slices). thread: d = tid&63, sub = tid>>6.
__global__ void rs1_kernel(float* __restrict__ psq, float* __restrict__ psk) {
    int bx = blockIdx.x;
    int bh = bx >> 4, part = bx & 15;
    int tid = threadIdx.x;
    int d = tid & 63, sub = tid >> 6;
    size_t base = (size_t)bh * HW_ * DH_ + d;
    int n0 = part * 64 + sub * 16;
    float sq = 0.f, sk = 0.f;
#pragma unroll
    for (int n = 0; n < 16; n++) {
        size_t off = base + (size_t)(n0 + n) * DH_;
        float qv = __bfloat162float(g_qhi[off]) + __bfloat162float(g_qlo[off]);
        float kv = __bfloat162float(g_khi[off]) + __bfloat162float(g_klo[off]);
        sq += qv * qv;
        sk += kv * kv;
    }
    __shared__ float smq[4][64], smk[4][64];
    smq[sub][d] = sq; smk[sub][d] = sk;
    __syncthreads();
    if (tid < 64) {
        float q = (smq[0][d] + smq[1][d]) + (smq[2][d] + smq[3][d]);
        float k = (smk[0][d] + smk[1][d]) + (smk[2][d] + smk[3][d]);
        psq[((size_t)bh * 16 + part) * 64 + d] = q;
        psk[((size_t)bh * 16 + part) * 64 + d] = k;
    }
}

// stage2: 64 blocks (bh), 64 threads (d): final sum + rs.
__global__ void rs2_kernel(const float* __restrict__ psq,
                           const float* __restrict__ psk,
                           const float* __restrict__ temp,
                           float* __restrict__ rs) {
    int bh = blockIdx.x, d = threadIdx.x;
    int h = bh % NH_;
    float q = 0.f, k = 0.f;
#pragma unroll
    for (int p = 0; p < 16; p++) {
        q += psq[((size_t)bh * 16 + p) * 64 + d];
        k += psk[((size_t)bh * 16 + p) * 64 + d];
    }
    float qn = fmaxf(sqrtf(q), 1e-12f);
    float kn = fmaxf(sqrtf(k), 1e-12f);
    rs[(size_t)bh * DH_ + d] = temp[h] / (qn * kn);
}

// ---------------- tensor-core fused flash attention --------------------------
#define FAT_STAGE 24576u
#define FAT_SMEM  (2 * 24576 + 256)

__device__ __forceinline__ void fat_loadkv(
    uint32_t buf, int tid, size_t kvbase, int kc,
    const bf16* __restrict__ khi,
    const bf16* __restrict__ vhi, const bf16* __restrict__ vlo) {
#pragma unroll
    for (int it = 0; it < 2; it++) {
        int idx = it * 256 + tid;
        int r = idx >> 3, cg = idx & 7;
        uint32_t so = SWZ((uint32_t)(r * 128 + cg * 16));
        size_t g = kvbase + (size_t)(kc + r) * DH_ + cg * 8;
        cp16(buf +     0u + so, khi + g);
        cp16(buf +  8192u + so, vhi + g);
        cp16(buf + 16384u + so, vlo + g);
    }
    asm volatile("cp.async.commit_group;" ::: "memory");
}

__global__ __launch_bounds__(256, 1)
void fat_kernel(const bf16* __restrict__ qhi, const bf16* __restrict__ qlo,
                const float* __restrict__ rs,
                const bf16* __restrict__ khi,
                const bf16* __restrict__ vhi, const bf16* __restrict__ vlo,
                bf16* __restrict__ ohi, bf16* __restrict__ olo) {
    extern __shared__ char smc[];
    uint32_t sb = smem_u32(smc);
    float* rss = (float*)(smc + 2 * FAT_STAGE);
    int bh = blockIdx.y;
    int b = bh >> 3, h = bh & 7;
    int q0 = blockIdx.x * 128;
    int tid = threadIdx.x, wid = tid >> 5, lane = tid & 31;
    int mb = wid * 16;

    if (tid < 64) rss[tid] = rs[bh * DH_ + tid];
    __syncthreads();

#pragma unroll
    for (int v = 0; v < 8; v++) {
        int idx = v * 256 + tid;
        int row = idx >> 4, dq = (idx & 15) * 4;
        size_t qoff = ((size_t)bh * HW_ + q0 + row) * DH_ + dq;
        __nv_bfloat162 ha = *(const __nv_bfloat162*)&qhi[qoff];
        __nv_bfloat162 hb = *(const __nv_bfloat162*)&qhi[qoff + 2];
        __nv_bfloat162 la = *(const __nv_bfloat162*)&qlo[qoff];
        __nv_bfloat162 lb = *(const __nv_bfloat162*)&qlo[qoff + 2];
        float qx = (__bfloat162float(ha.x) + __bfloat162float(la.x)) * rss[dq];
        float qy = (__bfloat162float(ha.y) + __bfloat162float(la.y)) * rss[dq + 1];
        float qz = (__bfloat162float(hb.x) + __bfloat162float(lb.x)) * rss[dq + 2];
        float qw = (__bfloat162float(hb.y) + __bfloat162float(lb.y)) * rss[dq + 3];
        uint32_t h0, l0, h1, l1;
        split2(qx, qy, h0, l0);
        split2(qz, qw, h1, l1);
        uint32_t off = SWZ((uint32_t)(row * 128 + dq * 2));
        *(uint32_t*)(smc + off)             = h0;
        *(uint32_t*)(smc + off + 4)         = h1;
        *(uint32_t*)(smc + 16384 + off)     = l0;
        *(uint32_t*)(smc + 16384 + off + 4) = l1;
    }
    __syncthreads();

    uint32_t qh[4][4], ql[4][4];
#pragma unroll
    for (int ks = 0; ks < 4; ks++) {
        uint32_t ao = SWZ((uint32_t)((mb + (lane & 15)) * 128 +
                                     (lane >> 4) * 16 + ks * 32));
        ldsm4(qh[ks], sb + ao);
        ldsm4(ql[ks], sb + 16384 + ao);
    }
    __syncthreads();

    float o[8][4];
#pragma unroll
    for (int j = 0; j < 8; j++)
#pragma unroll
        for (int q = 0; q < 4; q++) o[j][q] = 0.f;
    float m0 = -1e30f, m1 = -1e30f, l0 = 0.f, l1 = 0.f;
    const size_t kvbase = (size_t)bh * HW_ * DH_;

    fat_loadkv(sb, tid, kvbase, 0, khi, vhi, vlo);
    for (int kt = 0; kt < 16; kt++) {
        uint32_t cur = sb + (uint32_t)(kt & 1) * FAT_STAGE;
        if (kt + 1 < 16) {
            fat_loadkv(sb + (uint32_t)((kt + 1) & 1) * FAT_STAGE, tid, kvbase,
                       (kt + 1) * 64, khi, vhi, vlo);
            asm volatile("cp.async.wait_group 1;" ::: "memory");
        } else {
            asm volatile("cp.async.wait_group 0;" ::: "memory");
        }
        __syncthreads();

        float s[8][4];
#pragma unroll
        for (int j = 0; j < 8; j++)
#pragma unroll
            for (int q = 0; q < 4; q++) s[j][q] = 0.f;
#pragma unroll
        for (int ks = 0; ks < 4; ks++) {
            uint32_t brow = (uint32_t)(((lane & 7) + ((lane >> 4) & 1) * 8) * 128 +
                                       ((lane >> 3) & 1) * 16 + ks * 32);
#pragma unroll
            for (int np = 0; np < 4; np++) {
                uint32_t bo = SWZ(brow + (uint32_t)(np * 16 * 128));
                uint32_t kh4[4];
                ldsm4(kh4, cur + bo);
#pragma unroll
                for (int half = 0; half < 2; half++) {
                    int j = np * 2 + half;
                    const uint32_t bhh[2] = {kh4[half * 2], kh4[half * 2 + 1]};
                    mma16816(s[j], qh[ks], bhh);
                    mma16816(s[j], ql[ks], bhh);
                }
            }
        }

        float mx0 = -1e30f, mx1 = -1e30f;
#pragma unroll
        for (int j = 0; j < 8; j++) {
            mx0 = fmaxf(mx0, fmaxf(s[j][0], s[j][1]));
            mx1 = fmaxf(mx1, fmaxf(s[j][2], s[j][3]));
        }
        mx0 = fmaxf(mx0, __shfl_xor_sync(0xffffffffu, mx0, 1));
        mx0 = fmaxf(mx0, __shfl_xor_sync(0xffffffffu, mx0, 2));
        mx1 = fmaxf(mx1, __shfl_xor_sync(0xffffffffu, mx1, 1));
        mx1 = fmaxf(mx1, __shfl_xor_sync(0xffffffffu, mx1, 2));
        float mn0 = fmaxf(m0, mx0), mn1 = fmaxf(m1, mx1);
        float al0 = __expf(m0 - mn0), al1 = __expf(m1 - mn1);
        float sum0 = 0.f, sum1 = 0.f;
#pragma unroll
        for (int j = 0; j < 8; j++) {
            s[j][0] = __expf(s[j][0] - mn0);
            s[j][1] = __expf(s[j][1] - mn0);
            s[j][2] = __expf(s[j][2] - mn1);
            s[j][3] = __expf(s[j][3] - mn1);
            sum0 += s[j][0] + s[j][1];
            sum1 += s[j][2] + s[j][3];
        }
        sum0 += __shfl_xor_sync(0xffffffffu, sum0, 1);
        sum0 += __shfl_xor_sync(0xffffffffu, sum0, 2);
        sum1 += __shfl_xor_sync(0xffffffffu, sum1, 1);
        sum1 += __shfl_xor_sync(0xffffffffu, sum1, 2);
        l0 = l0 * al0 + sum0; l1 = l1 * al1 + sum1;
        m0 = mn0; m1 = mn1;
#pragma unroll
        for (int j = 0; j < 8; j++) {
            o[j][0] *= al0; o[j][1] *= al0;
            o[j][2] *= al1; o[j][3] *= al1;
        }

#pragma unroll
        for (int ks = 0; ks < 4; ks++) {
            int j0 = 2 * ks, j1 = 2 * ks + 1;
            uint32_t ph[4], pl[4];
            split2(s[j0][0], s[j0][1], ph[0], pl[0]);
            split2(s[j0][2], s[j0][3], ph[1], pl[1]);
            split2(s[j1][0], s[j1][1], ph[2], pl[2]);
            split2(s[j1][2], s[j1][3], ph[3], pl[3]);
            uint32_t vrow = (uint32_t)((ks * 16 + (lane & 7) + ((lane >> 3) & 1) * 8) * 128 +
                                       ((lane >> 4) & 1) * 16);
#pragma unroll
            for (int np = 0; np < 4; np++) {
                uint32_t vo = SWZ(vrow + (uint32_t)(np * 32));
                uint32_t vh4[4], vl4[4];
                ldsm4t(vh4, cur +  8192u + vo);
                ldsm4t(vl4, cur + 16384u + vo);
#pragma unroll
                for (int half = 0; half < 2; half++) {
                    int j = np * 2 + half;
                    const uint32_t bvh[2] = {vh4[half * 2], vh4[half * 2 + 1]};
                    const uint32_t bvl[2] = {vl4[half * 2], vl4[half * 2 + 1]};
                    mma16816(o[j], ph, bvh);
                    mma16816(o[j], ph, bvl);
                    mma16816(o[j], pl, bvh);
                }
            }
        }
        __syncthreads();
    }

    float inv0 = 1.f / l0, inv1 = 1.f / l1;
    int r0 = lane >> 2, cc = (lane & 3) * 2;
    int row0 = q0 + mb + r0, row1 = row0 + 8;
#pragma unroll
    for (int j = 0; j < 8; j++) {
        int col = h * DH_ + j * 8 + cc;
        size_t off0 = ((size_t)(b * HW_ + row0)) * C_ + col;
        size_t off1 = ((size_t)(b * HW_ + row1)) * C_ + col;
        uint32_t hi, lo;
        split2(o[j][0] * inv0, o[j][1] * inv0, hi, lo);
        *(uint32_t*)&ohi[off0] = hi; *(uint32_t*)&olo[off0] = lo;
        split2(o[j][2] * inv1, o[j][3] * inv1, hi, lo);
        *(uint32_t*)&ohi[off1] = hi; *(uint32_t*)&olo[off1] = lo;
    }
}

// ---------------- LayerNorm over C + residual + transpose to [B,C,HW] -------
__global__ void ln_residual_kernel(const float* __restrict__ ob,
                                   const float* __restrict__ x,
                                   const float* __restrict__ g,
                                   const float* __restrict__ be,
                                   float* __restrict__ y) {
    int row = blockIdx.x;
    int b = row >> 10, n = row & 1023;
    const float* pr = ob + (size_t)row * C_;
    int tid = threadIdx.x;
    float v0 = pr[tid], v1 = pr[tid + 256];
    __shared__ float red[256];
    red[tid] = v0 + v1; __syncthreads();
    for (int s = 128; s > 0; s >>= 1) {
        if (tid < s) red[tid] += red[tid + s];
        __syncthreads();
    }
    float mean = red[0] * (1.0f / C_);
    __syncthreads();
    float d0 = v0 - mean, d1 = v1 - mean;
    red[tid] = d0 * d0 + d1 * d1; __syncthreads();
    for (int s = 128; s > 0; s >>= 1) {
        if (tid < s) red[tid] += red[tid + s];
        __syncthreads();
    }
    float rstd = rsqrtf(red[0] * (1.0f / C_) + 1e-5f);
    int c0 = tid, c1 = tid + 256;
    size_t i0 = ((size_t)b * C_ + c0) * HW_ + n;
    size_t i1 = ((size_t)b * C_ + c1) * HW_ + n;
    y[i0] = d0 * rstd * g[c0] + be[c0] + x[i0];
    y[i1] = d1 * rstd * g[c1] + be[c1] + x[i1];
}

// ---------------- fused depthwise 3x3 + transpose + split --------------------
__global__ void dwt_kernel(const float* __restrict__ y,
                           const float* __restrict__ w,
                           const float* __restrict__ bias,
                           bf16* __restrict__ hi, bf16* __restrict__ lo) {
    __shared__ float yt[32][3][33];
    __shared__ float ot[32][33];   // [w][c]
    int hh = blockIdx.x, c0 = blockIdx.y * 32, b = blockIdx.z;
    int tid = threadIdx.x;
    int c = tid >> 3, wg = (tid & 7) * 4;

#pragma unroll
    for (int r = 0; r < 3; r++) {
        int ih = hh + r - 1;
        float4 v = make_float4(0.f, 0.f, 0.f, 0.f);
        if (ih >= 0 && ih < H_)
            v = *(const float4*)&y[((size_t)(b * C_ + c0 + c)) * HW_ + ih * W_ + wg];
        yt[c][r][wg + 0] = v.x; yt[c][r][wg + 1] = v.y;
        yt[c][r][wg + 2] = v.z; yt[c][r][wg + 3] = v.w;
    }
    float wc[9];
#pragma unroll
    for (int i = 0; i < 9; i++) wc[i] = w[(c0 + c) * 9 + i];
    float bs = bias[c0 + c];
    __syncthreads();

#pragma unroll
    for (int j = 0; j < 4; j++) {
        int ww = wg + j;
        float acc = bs;
#pragma unroll
        for (int ki = 0; ki < 3; ki++)
#pragma unroll
            for (int kj = 0; kj < 3; kj++) {
                int iw = ww + kj - 1;
                if (iw >= 0 && iw < W_) acc += wc[ki * 3 + kj] * yt[c][ki][iw];
            }
        ot[ww][c] = acc;
    }
    __syncthreads();

    int w2 = tid >> 3, cg = (tid & 7) * 4;
    int token = hh * W_ + w2;
    size_t base = ((size_t)b * HW_ + token) * C_ + c0 + cg;
    float a0 = ot[w2][cg], a1 = ot[w2][cg + 1];
    float a2 = ot[w2][cg + 2], a3 = ot[w2][cg + 3];
    uint32_t h0, l0, h1, l1;
    split2(a0, a1, h0, l0);
    split2(a2, a3, h1, l1);
    *(uint32_t*)&hi[base]     = h0; *(uint32_t*)&hi[base + 2] = h1;
    *(uint32_t*)&lo[base]     = l0; *(uint32_t*)&lo[base + 2] = l1;
}

// ---------------- launch ------------------------------------------------------
extern "C" void kernel_launch(void* const* d_in, const int* in_sizes, int n_in,
                              void* d_out, int out_size) {
    const float* x      = (const float*)d_in[0];
    const float* qkv_w  = (const float*)d_in[1];
    const float* proj_w = (const float*)d_in[2];
    const float* proj_b = (const float*)d_in[3];
    const float* temper = (const float*)d_in[4];
    const float* ln_g   = (const float*)d_in[5];
    const float* ln_b   = (const float*)d_in[6];
    const float* pos    = (const float*)d_in[7];
    const float* dw_w   = (const float*)d_in[8];
    const float* dw_b   = (const float*)d_in[9];
    const float* pw_w   = (const float*)d_in[10];
    const float* pw_b   = (const float*)d_in[11];
    float* out = (float*)d_out;

    bf16 *thi, *tlo, *w1hi, *w1lo, *w2hi, *w2lo, *w3hi, *w3lo;
    bf16 *ohi, *olo, *dThi, *dTlo, *qhi, *qlo, *khi, *vhi, *vlo;
    float *rs, *ob, *y, *psq, *psk;
    cudaGetSymbolAddress((void**)&thi,  g_thi);
    cudaGetSymbolAddress((void**)&tlo,  g_tlo);
    cudaGetSymbolAddress((void**)&w1hi, g_w1hi);
    cudaGetSymbolAddress((void**)&w1lo, g_w1lo);
    cudaGetSymbolAddress((void**)&w2hi, g_w2hi);
    cudaGetSymbolAddress((void**)&w2lo, g_w2lo);
    cudaGetSymbolAddress((void**)&w3hi, g_w3hi);
    cudaGetSymbolAddress((void**)&w3lo, g_w3lo);
    cudaGetSymbolAddress((void**)&ohi,  g_ohi);
    cudaGetSymbolAddress((void**)&olo,  g_olo);
    cudaGetSymbolAddress((void**)&dThi, g_dThi);
    cudaGetSymbolAddress((void**)&dTlo, g_dTlo);
    cudaGetSymbolAddress((void**)&qhi,  g_qhi);
    cudaGetSymbolAddress((void**)&qlo,  g_qlo);
    cudaGetSymbolAddress((void**)&khi,  g_khi);
    cudaGetSymbolAddress((void**)&vhi,  g_vhi);
    cudaGetSymbolAddress((void**)&vlo,  g_vlo);
    cudaGetSymbolAddress((void**)&rs,   g_rs);
    cudaGetSymbolAddress((void**)&psq,  g_psq);
    cudaGetSymbolAddress((void**)&psk,  g_psk);
    cudaGetSymbolAddress((void**)&ob,   g_ob);
    cudaGetSymbolAddress((void**)&y,    g_y);

    cudaFuncSetAttribute(fat_kernel,
                         cudaFuncAttributeMaxDynamicSharedMemorySize, FAT_SMEM);
    cudaFuncSetAttribute(gemm_tc,
                         cudaFuncAttributeMaxDynamicSharedMemorySize, GSMEM);

    // fused weight splits
    splitw_kernel<<<(NW1 + 2*NW2 + 255)/256, 256>>>(qkv_w, proj_w, pw_w);
    // t = transpose(x) + pos (bf16 split)
    build_t_kernel<<<dim3(HW_/32, C_/32, B_), dim3(32, 8)>>>(x, pos, thi, tlo);
    // qkv GEMM: q,k columns 2-term; v columns 3-term; split head-major output
    gemm_tc<<<dim3(C3_/128, (B_*HW_)/128, 1), 256, GSMEM>>>(
        thi, tlo, w1hi, w1lo, nullptr, nullptr, nullptr, C_, 0, 0, 0,
        1 /*mode=qkv*/, 1024 /*n2term: v cols 3-term*/);
    // rs two-stage reduction (parallel, deterministic)
    rs1_kernel<<<B_*NH_*16, 256>>>(psq, psk);
    rs2_kernel<<<B_*NH_, 64>>>(psq, psk, temper, rs);
    // tensor-core fused attention -> o (bf16 split)
    fat_kernel<<<dim3(HW_/128, B_*NH_), 256, FAT_SMEM>>>(
        qhi, qlo, rs, khi, vhi, vlo, ohi, olo);
    // proj = o @ proj_w^T + proj_b (full 3-term)
    gemm_tc<<<dim3(C_/128, (B_*HW_)/128, 1), 256, GSMEM>>>(
        ohi, olo, w2hi, w2lo, proj_b, nullptr, ob, C_, C_, 0, 0, 0, 0);
    // LN + residual + transpose to [B,C,HW]
    ln_residual_kernel<<<B_*HW_, 256>>>(ob, x, ln_g, ln_b, y);
    // fused depthwise 3x3 + transpose + split
    dwt_kernel<<<dim3(H_, C_/32, B_), 256>>>(y, dw_w, dw_b, dThi, dTlo);
    // pointwise (2-term) + bias + residual -> out
    gemm_tc<<<dim3(HW_/128, C_/128, B_), 256, GSMEM>>>(
        w3hi, w3lo, dThi, dTlo, pw_b, y, out, C_, HW_,
        (long)HW_*C_, (long)C_*HW_, 0, 1 << 30);
}